// round 2
// baseline (speedup 1.0000x reference)
#include <cuda_runtime.h>
#include <math.h>

#define Nn 50000
#define Ee 600000
#define Rr 64
#define Vv 49936
#define HDim 128
#define NHEAD 4
#define EDim 8

// ---------------- scratch (__device__ globals; no cudaMalloc) ---------------
__device__ float g_h[Nn * HDim];
__device__ float g_x2[Nn * HDim];
__device__ float g_scat[Nn * HDim];
__device__ float g_acc[Nn * HDim];
__device__ float g_ssrc[Nn * NHEAD];
__device__ float g_sdst[Nn * NHEAD];
__device__ float g_aloop[Nn * NHEAD];
__device__ float g_m[Nn * NHEAD];
__device__ float g_den[Nn * NHEAD];
__device__ float g_alpha[(size_t)Ee * NHEAD];
__device__ float g_aw[(size_t)Rr * Vv];
__device__ float g_scores[Vv];
__device__ float g_pmax[Rr], g_pden[Rr];
__device__ int   g_pcnt[Rr];
__device__ float g_pooled[Rr * HDim];
__device__ float g_q1[Rr * HDim];
__device__ float g_q2[Rr * 64];
__device__ float g_gate[3], g_wts[3];
__device__ float g_Wt[3][2][HDim];
__device__ float g_v1[3][NHEAD][EDim];
__device__ float g_v2[3][EDim];
__device__ float g_edl1[3][NHEAD];
__device__ float g_edl2[3];
__device__ float g_easum[3][EDim];

// ---------------- helpers ----------------------------------------------------
__device__ __forceinline__ void atomicMaxF(float* addr, float v) {
    if (v >= 0.f) atomicMax((int*)addr, __float_as_int(v));
    else          atomicMin((unsigned int*)addr, __float_as_uint(v));
}
__device__ __forceinline__ void redAdd4(float* addr, float a, float b, float c, float d) {
    asm volatile("red.global.add.v4.f32 [%0], {%1,%2,%3,%4};"
                 :: "l"(addr), "f"(a), "f"(b), "f"(c), "f"(d) : "memory");
}

// ---------------- setup -------------------------------------------------------
__global__ void k_zero_easum() {
    int t = threadIdx.x;
    if (t < 24) ((float*)g_easum)[t] = 0.f;
}

__global__ void k_easum(const float* __restrict__ ea0, const float* __restrict__ ea1,
                        const float* __restrict__ ea2) {
    const float* ea = blockIdx.y == 0 ? ea0 : (blockIdx.y == 1 ? ea1 : ea2);
    __shared__ float s[EDim];
    if (threadIdx.x < EDim) s[threadIdx.x] = 0.f;
    __syncthreads();
    float loc[EDim];
#pragma unroll
    for (int k = 0; k < EDim; k++) loc[k] = 0.f;
    int base = blockIdx.x * 4096;
    int lim = base + 4096; if (lim > Ee) lim = Ee;
    for (int e = base + threadIdx.x; e < lim; e += 256) {
        const float4* p = (const float4*)(ea + (size_t)e * 8);
        float4 a = p[0], b = p[1];
        loc[0] += a.x; loc[1] += a.y; loc[2] += a.z; loc[3] += a.w;
        loc[4] += b.x; loc[5] += b.y; loc[6] += b.z; loc[7] += b.w;
    }
#pragma unroll
    for (int k = 0; k < EDim; k++) atomicAdd(&s[k], loc[k]);
    __syncthreads();
    if (threadIdx.x < EDim) atomicAdd(&g_easum[blockIdx.y][threadIdx.x], s[threadIdx.x]);
}

__global__ void k_setup(const float* __restrict__ temb, const float* __restrict__ etg,
                        const float* __restrict__ eta, const float* __restrict__ W1,
                        const float* __restrict__ We1, const float* __restrict__ ae1,
                        const float* __restrict__ We2, const float* __restrict__ ae2) {
    int t = threadIdx.x;
    if (t < 3) g_gate[t] = 1.f / (1.f + __expf(-etg[t]));
    if (t == 0) {
        float m = fmaxf(eta[0], fmaxf(eta[1], eta[2]));
        float e0 = __expf(eta[0] - m), e1 = __expf(eta[1] - m), e2 = __expf(eta[2] - m);
        float s = e0 + e1 + e2;
        g_wts[0] = e0 / s; g_wts[1] = e1 / s; g_wts[2] = e2 / s;
    }
    __syncthreads();
    for (int idx = t; idx < 3 * 2 * HDim; idx += 256) {
        int i = idx / (2 * HDim); int r = idx % (2 * HDim);
        int ty = r / HDim; int j = r % HDim;
        float s = 0.f;
        for (int k = 0; k < 32; k++)
            s += temb[ty * 32 + k] * W1[i * 41 * HDim + (9 + k) * HDim + j];
        g_Wt[i][ty][j] = s;
    }
    for (int idx = t; idx < 3 * NHEAD * EDim; idx += 256) {
        int i = idx / 32; int h = (idx % 32) / 8; int k = idx % 8;
        float s = 0.f;
        for (int c = 0; c < 32; c++)
            s += We1[i * EDim * HDim + k * HDim + h * 32 + c] * ae1[i * NHEAD * 32 + h * 32 + c];
        g_v1[i][h][k] = g_gate[i] * s;
    }
    for (int idx = t; idx < 3 * EDim; idx += 256) {
        int i = idx / 8; int k = idx % 8;
        float s = 0.f;
        for (int c = 0; c < HDim; c++)
            s += We2[i * EDim * HDim + k * HDim + c] * ae2[i * HDim + c];
        g_v2[i][k] = g_gate[i] * s;
    }
    __syncthreads();
    if (t < 12) {
        int i = t / 4, h = t % 4;
        float s = 0.f;
        for (int k = 0; k < EDim; k++) s += (g_easum[i][k] / (float)Ee) * g_v1[i][h][k];
        g_edl1[i][h] = s;
    }
    if (t >= 32 && t < 35) {
        int i = t - 32;
        float s = 0.f;
        for (int k = 0; k < EDim; k++) s += (g_easum[i][k] / (float)Ee) * g_v2[i][k];
        g_edl2[i] = s;
    }
}

// ---------------- layer 1 projection + per-node attn logits ------------------
__global__ void k_proj1(const float* __restrict__ nf, const int* __restrict__ ntype,
                        const float* __restrict__ W1i, const float* __restrict__ as1,
                        const float* __restrict__ ad1, int i) {
    int j = threadIdx.x; int h = j >> 5;
    float w[9];
#pragma unroll
    for (int k = 0; k < 9; k++) w[k] = W1i[k * HDim + j];
    float wt0 = g_Wt[i][0][j], wt1 = g_Wt[i][1][j];
    float as = as1[j], ad = ad1[j];
    int nb = blockIdx.x * 4;
#pragma unroll
    for (int nn = 0; nn < 4; nn++) {
        int n = nb + nn;
        const float* row = nf + (size_t)n * 9;
        float acc = ntype[n] ? wt1 : wt0;
#pragma unroll
        for (int k = 0; k < 9; k++) acc += row[k] * w[k];
        g_h[(size_t)n * HDim + j] = acc;
        float ss = acc * as, sd = acc * ad;
#pragma unroll
        for (int o = 16; o > 0; o >>= 1) {
            ss += __shfl_xor_sync(0xffffffffu, ss, o);
            sd += __shfl_xor_sync(0xffffffffu, sd, o);
        }
        if ((j & 31) == 0) { g_ssrc[n * NHEAD + h] = ss; g_sdst[n * NHEAD + h] = sd; }
    }
}

__global__ void k_node_init(int i, int Hcur) {
    int idx = blockIdx.x * blockDim.x + threadIdx.x;
    if (idx < Nn * HDim) g_scat[idx] = 0.f;
    if (idx < Nn * Hcur) {
        int h = idx % Hcur;
        float a = g_ssrc[idx] + g_sdst[idx] + (Hcur == 4 ? g_edl1[i][h] : g_edl2[i]);
        a = a > 0.f ? a : 0.2f * a;
        g_aloop[idx] = a; g_m[idx] = a; g_den[idx] = 0.f;
    }
}

template <int HH>
__global__ void k_edge_alpha(const int* __restrict__ ei, const float* __restrict__ ea, int i) {
    int e = blockIdx.x * blockDim.x + threadIdx.x;
    if (e >= Ee) return;
    int src = ei[e], dst = ei[Ee + e];
    const float4* eap = (const float4*)(ea + (size_t)e * 8);
    float4 a0 = eap[0], a1 = eap[1];
    if (HH == 4) {
#pragma unroll
        for (int h = 0; h < 4; h++) {
            const float* v = g_v1[i][h];
            float ed = a0.x * v[0] + a0.y * v[1] + a0.z * v[2] + a0.w * v[3]
                     + a1.x * v[4] + a1.y * v[5] + a1.z * v[6] + a1.w * v[7];
            float a = g_ssrc[src * 4 + h] + g_sdst[dst * 4 + h] + ed;
            a = a > 0.f ? a : 0.2f * a;
            g_alpha[(size_t)e * 4 + h] = a;
            atomicMaxF(&g_m[dst * 4 + h], a);
        }
    } else {
        const float* v = g_v2[i];
        float ed = a0.x * v[0] + a0.y * v[1] + a0.z * v[2] + a0.w * v[3]
                 + a1.x * v[4] + a1.y * v[5] + a1.z * v[6] + a1.w * v[7];
        float a = g_ssrc[src] + g_sdst[dst] + ed;
        a = a > 0.f ? a : 0.2f * a;
        g_alpha[e] = a;
        atomicMaxF(&g_m[dst], a);
    }
}

template <int HH>
__global__ void k_edge_bc(const int* __restrict__ ei) {
    int e = blockIdx.x * 8 + (threadIdx.x >> 5);
    if (e >= Ee) return;
    int lane = threadIdx.x & 31;
    int src = ei[e], dst = ei[Ee + e];
    float myE;
    if (HH == 4) {
        float ev = 0.f;
        if (lane < 4) {
            float a = g_alpha[(size_t)e * 4 + lane];
            ev = __expf(a - g_m[dst * 4 + lane]);
            atomicAdd(&g_den[dst * 4 + lane], ev);
        }
        float e0 = __shfl_sync(0xffffffffu, ev, 0);
        float e1 = __shfl_sync(0xffffffffu, ev, 1);
        float e2 = __shfl_sync(0xffffffffu, ev, 2);
        float e3 = __shfl_sync(0xffffffffu, ev, 3);
        int hh = lane >> 3;
        myE = hh == 0 ? e0 : (hh == 1 ? e1 : (hh == 2 ? e2 : e3));
    } else {
        float ev = 0.f;
        if (lane == 0) {
            ev = __expf(g_alpha[e] - g_m[dst]);
            atomicAdd(&g_den[dst], ev);
        }
        myE = __shfl_sync(0xffffffffu, ev, 0);
    }
    const float4* hp = (const float4*)(g_h + (size_t)src * HDim);
    float4 hv = hp[lane];
    redAdd4(g_scat + (size_t)dst * HDim + lane * 4,
            hv.x * myE, hv.y * myE, hv.z * myE, hv.w * myE);
}

__global__ void k_node_fin1(const float* __restrict__ b1) {
    int idx = blockIdx.x * blockDim.x + threadIdx.x;
    if (idx >= Nn * HDim) return;
    int n = idx >> 7; int j = idx & 127; int h = j >> 5;
    float es = __expf(g_aloop[n * 4 + h] - g_m[n * 4 + h]);
    float den = g_den[n * 4 + h] + es + 1e-16f;
    float v = (g_scat[idx] + g_h[idx] * es) / den + b1[j];
    g_x2[idx] = v > 0.f ? v : (expf(v) - 1.f);
}

__global__ void k_node_fin2(const float* __restrict__ b2, int i, int first) {
    int idx = blockIdx.x * blockDim.x + threadIdx.x;
    if (idx >= Nn * HDim) return;
    int n = idx >> 7; int j = idx & 127;
    float es = __expf(g_aloop[n] - g_m[n]);
    float den = g_den[n] + es + 1e-16f;
    float v = (g_scat[idx] + g_h[idx] * es) / den + b2[j];
    float w = g_wts[i];
    if (first) g_acc[idx] = w * v; else g_acc[idx] += w * v;
}

// ---------------- 128-wide SGEMM: g_h = g_x2 @ W ------------------------------
__global__ void gemm128(const float* __restrict__ W) {
    __shared__ __align__(16) float Xs[32][68];
    __shared__ __align__(16) float Ws[32][128];
    int tid = threadIdx.x;
    int ty = tid >> 4;
    int tx = tid & 15;
    int nb = blockIdx.x * 64;
    float acc[4][8];
#pragma unroll
    for (int q = 0; q < 4; q++)
#pragma unroll
        for (int p = 0; p < 8; p++) acc[q][p] = 0.f;

    for (int kt = 0; kt < 4; kt++) {
#pragma unroll
        for (int i = 0; i < 8; i++) {
            int el = tid + i * 256;
            int nn = el >> 5; int kk = el & 31;
            int n = nb + nn;
            Xs[kk][nn] = (n < Nn) ? g_x2[(size_t)n * 128 + kt * 32 + kk] : 0.f;
        }
#pragma unroll
        for (int i = 0; i < 16; i++) {
            int el = tid + i * 256;
            int kk = el >> 7; int j = el & 127;
            Ws[kk][j] = W[(kt * 32 + kk) * 128 + j];
        }
        __syncthreads();
#pragma unroll
        for (int kk = 0; kk < 32; kk++) {
            float4 xv = *(const float4*)&Xs[kk][ty * 4];
            float4 w0 = *(const float4*)&Ws[kk][tx * 8];
            float4 w1 = *(const float4*)&Ws[kk][tx * 8 + 4];
            float xq[4] = {xv.x, xv.y, xv.z, xv.w};
            float wq[8] = {w0.x, w0.y, w0.z, w0.w, w1.x, w1.y, w1.z, w1.w};
#pragma unroll
            for (int q = 0; q < 4; q++)
#pragma unroll
                for (int p = 0; p < 8; p++) acc[q][p] += xq[q] * wq[p];
        }
        __syncthreads();
    }
#pragma unroll
    for (int q = 0; q < 4; q++) {
        int n = nb + ty * 4 + q;
        if (n < Nn) {
            float4 o0 = make_float4(acc[q][0], acc[q][1], acc[q][2], acc[q][3]);
            float4 o1 = make_float4(acc[q][4], acc[q][5], acc[q][6], acc[q][7]);
            *(float4*)&g_h[(size_t)n * 128 + tx * 8] = o0;
            *(float4*)&g_h[(size_t)n * 128 + tx * 8 + 4] = o1;
        }
    }
}

__global__ void k_s2(const float* __restrict__ as2, const float* __restrict__ ad2) {
    int n = blockIdx.x * 8 + (threadIdx.x >> 5);
    if (n >= Nn) return;
    int lane = threadIdx.x & 31;
    float ss = 0.f, sd = 0.f;
#pragma unroll
    for (int k = 0; k < 4; k++) {
        int j = lane + k * 32;
        float hv = g_h[(size_t)n * HDim + j];
        ss += hv * as2[j]; sd += hv * ad2[j];
    }
#pragma unroll
    for (int o = 16; o > 0; o >>= 1) {
        ss += __shfl_xor_sync(0xffffffffu, ss, o);
        sd += __shfl_xor_sync(0xffffffffu, sd, o);
    }
    if (lane == 0) { g_ssrc[n] = ss; g_sdst[n] = sd; }
}

// ---------------- pooling / readout -------------------------------------------
__global__ void k_scores(const float* __restrict__ pW, const float* __restrict__ pb) {
    int v = blockIdx.x * 8 + (threadIdx.x >> 5);
    if (v >= Vv) return;
    int lane = threadIdx.x & 31;
    float s = 0.f;
#pragma unroll
    for (int k = 0; k < 4; k++) {
        int j = lane + k * 32;
        s += g_acc[(size_t)(Rr + v) * HDim + j] * pW[j];
    }
#pragma unroll
    for (int o = 16; o > 0; o >>= 1) s += __shfl_xor_sync(0xffffffffu, s, o);
    if (lane == 0) g_scores[v] = s + pb[0];
}

__global__ void k_stats(const int* __restrict__ mask) {
    int r = blockIdx.x; int t = threadIdx.x;
    __shared__ float red[256];
    __shared__ int redi[256];
    const int* mrow = mask + (size_t)r * Vv;
    float mx = -3.0e38f;
    for (int v = t; v < Vv; v += 256) if (mrow[v]) mx = fmaxf(mx, g_scores[v]);
    red[t] = mx; __syncthreads();
    for (int s = 128; s > 0; s >>= 1) { if (t < s) red[t] = fmaxf(red[t], red[t + s]); __syncthreads(); }
    float m = red[0]; __syncthreads();
    float sm = 0.f; int c = 0;
    for (int v = t; v < Vv; v += 256)
        if (mrow[v]) { sm += __expf(g_scores[v] - m); c++; }
    red[t] = sm; redi[t] = c; __syncthreads();
    for (int s = 128; s > 0; s >>= 1) {
        if (t < s) { red[t] += red[t + s]; redi[t] += redi[t + s]; }
        __syncthreads();
    }
    if (t == 0) { g_pmax[r] = m; g_pden[r] = red[0]; g_pcnt[r] = redi[0]; }
    if (t < HDim) g_pooled[r * HDim + t] = 0.f;
}

__global__ void k_aw(const int* __restrict__ mask) {
    int v = blockIdx.x * 256 + threadIdx.x;
    int r = blockIdx.y;
    if (v >= Vv) return;
    float aw = 0.f;
    if (g_pcnt[r] > 0 && mask[(size_t)r * Vv + v])
        aw = __expf(g_scores[v] - g_pmax[r]) / g_pden[r];
    g_aw[(size_t)r * Vv + v] = aw;
}

__global__ void k_pooled() {
    __shared__ float aws[64 * 128];
    int t = threadIdx.x;
    int vb = blockIdx.x * 128;
    int nv = Vv - vb; if (nv > 128) nv = 128;
    for (int idx = t; idx < 64 * 128; idx += 256) {
        int r = idx >> 7, v = idx & 127;
        aws[idx] = (v < nv) ? g_aw[(size_t)r * Vv + vb + v] : 0.f;
    }
    __syncthreads();
    int rg = t >> 7, c = t & 127;
    float acc[32];
#pragma unroll
    for (int rr = 0; rr < 32; rr++) acc[rr] = 0.f;
    for (int v = 0; v < nv; v++) {
        float vx = g_acc[(size_t)(Rr + vb + v) * HDim + c];
#pragma unroll
        for (int rr = 0; rr < 32; rr++) acc[rr] += aws[(rg * 32 + rr) * 128 + v] * vx;
    }
    for (int rr = 0; rr < 32; rr++)
        atomicAdd(&g_pooled[(rg * 32 + rr) * 128 + c], acc[rr]);
}

__global__ void k_q1(const float* __restrict__ Wo1, const float* __restrict__ bo1) {
    __shared__ float comb[256];
    int r = blockIdx.x, t = threadIdx.x;
    comb[t] = g_acc[r * HDim + t];
    comb[128 + t] = g_pooled[r * HDim + t];
    __syncthreads();
    float a = bo1[t];
    for (int k = 0; k < 256; k++) a += comb[k] * Wo1[k * 128 + t];
    g_q1[r * 128 + t] = fmaxf(a, 0.f);
}

__global__ void k_q2(const float* __restrict__ Wo2, const float* __restrict__ bo2) {
    __shared__ float q[128];
    int r = blockIdx.x, t = threadIdx.x;
    q[t] = g_q1[r * 128 + t]; q[64 + t] = g_q1[r * 128 + 64 + t];
    __syncthreads();
    float a = bo2[t];
    for (int k = 0; k < 128; k++) a += q[k] * Wo2[k * 64 + t];
    g_q2[r * 64 + t] = fmaxf(a, 0.f);
}

__global__ void k_q3(const float* __restrict__ Wo3, const float* __restrict__ bo3,
                     const float* __restrict__ eta, float* __restrict__ out, int out_size) {
    __shared__ float q[64];
    int r = blockIdx.x, t = threadIdx.x;
    q[t] = g_q2[r * 64 + t]; q[32 + t] = g_q2[r * 64 + 32 + t];
    __syncthreads();
    if (t < 16) {
        float a = bo3[t];
        for (int k = 0; k < 64; k++) a += q[k] * Wo3[k * 16 + t];
        int oi = r * 16 + t;
        if (oi < out_size) out[oi] = a;
    }
    if (r == 0 && t >= 16 && t < 19) {
        int oi = 1024 + (t - 16);
        if (oi < out_size) out[oi] = eta[t - 16];
    }
}

// ---------------- launch --------------------------------------------------------
extern "C" void kernel_launch(void* const* d_in, const int* in_sizes, int n_in,
                              void* d_out, int out_size) {
    const float* nf    = (const float*)d_in[0];
    const float* eaA[3] = {(const float*)d_in[1], (const float*)d_in[2], (const float*)d_in[3]};
    const float* temb  = (const float*)d_in[4];
    const float* etg   = (const float*)d_in[5];
    const float* eta   = (const float*)d_in[6];
    const float* W1    = (const float*)d_in[7];
    const float* as1   = (const float*)d_in[8];
    const float* ad1   = (const float*)d_in[9];
    const float* We1   = (const float*)d_in[10];
    const float* ae1   = (const float*)d_in[11];
    const float* b1    = (const float*)d_in[12];
    const float* W2    = (const float*)d_in[13];
    const float* as2   = (const float*)d_in[14];
    const float* ad2   = (const float*)d_in[15];
    const float* We2   = (const float*)d_in[16];
    const float* ae2   = (const float*)d_in[17];
    const float* b2    = (const float*)d_in[18];
    const float* pW    = (const float*)d_in[19];
    const float* pb    = (const float*)d_in[20];
    const float* Wo1   = (const float*)d_in[21];
    const float* bo1   = (const float*)d_in[22];
    const float* Wo2   = (const float*)d_in[23];
    const float* bo2   = (const float*)d_in[24];
    const float* Wo3   = (const float*)d_in[25];
    const float* bo3   = (const float*)d_in[26];
    const int* ntype   = (const int*)d_in[27];
    const int* eiA[3]  = {(const int*)d_in[28], (const int*)d_in[29], (const int*)d_in[30]};
    const int* mask    = (const int*)d_in[31];
    float* out = (float*)d_out;

    k_zero_easum<<<1, 32>>>();
    { dim3 g(147, 3); k_easum<<<g, 256>>>(eaA[0], eaA[1], eaA[2]); }
    k_setup<<<1, 256>>>(temb, etg, eta, W1, We1, ae1, We2, ae2);

    for (int i = 0; i < 3; i++) {
        k_proj1<<<12500, 128>>>(nf, ntype, W1 + i * 41 * 128, as1 + i * 128, ad1 + i * 128, i);
        k_node_init<<<25000, 256>>>(i, 4);
        k_edge_alpha<4><<<2344, 256>>>(eiA[i], eaA[i], i);
        k_edge_bc<4><<<75000, 256>>>(eiA[i]);
        k_node_fin1<<<25000, 256>>>(b1 + i * 128);
        gemm128<<<782, 256>>>(W2 + i * 128 * 128);
        k_s2<<<6250, 256>>>(as2 + i * 128, ad2 + i * 128);
        k_node_init<<<25000, 256>>>(i, 1);
        k_edge_alpha<1><<<2344, 256>>>(eiA[i], eaA[i], i);
        k_edge_bc<1><<<75000, 256>>>(eiA[i]);
        k_node_fin2<<<25000, 256>>>(b2 + i * 128, i, i == 0 ? 1 : 0);
    }

    k_scores<<<6242, 256>>>(pW, pb);
    k_stats<<<64, 256>>>(mask);
    { dim3 g(196, 64); k_aw<<<g, 256>>>(mask); }
    k_pooled<<<391, 256>>>();
    k_q1<<<64, 128>>>(Wo1, bo1);
    k_q2<<<64, 64>>>(Wo2, bo2);
    k_q3<<<64, 32>>>(Wo3, bo3, eta, out, out_size);
}

// round 3
// speedup vs baseline: 1.5634x; 1.5634x over previous
#include <cuda_runtime.h>
#include <math.h>

#define Nn 50000
#define Ee 600000
#define Rr 64
#define Vv 49936
#define HDim 128
#define NHEAD 4
#define EDim 8
#define NCHUNK 98   // ceil(50000/512)

// ---------------- scratch (__device__ globals; no cudaMalloc) ---------------
__device__ float g_h[(size_t)Nn * HDim];
__device__ float g_x2[(size_t)Nn * HDim];
__device__ float g_acc[(size_t)Nn * HDim];
__device__ float g_ssrc[Nn * NHEAD];
__device__ float g_sdst[Nn * NHEAD];
__device__ float g_aloop[Nn * NHEAD];
__device__ int   g_deg[Nn];
__device__ int   g_cursor[Nn];
__device__ int   g_rowptr[Nn + 1];
__device__ int   g_bsum[NCHUNK];
__device__ int   g_csr_src[Ee];
__device__ int   g_csr_eid[Ee];
__device__ float g_edot1[(size_t)Ee * 4];
__device__ float g_edot2[Ee];
__device__ float g_scores[Vv];
__device__ float g_pmax[Rr], g_pden[Rr];
__device__ int   g_pcnt[Rr];
__device__ float g_pooled[Rr * HDim];
__device__ float g_q1[Rr * HDim];
__device__ float g_q2[Rr * 64];
__device__ float g_gate[3], g_wts[3];
__device__ float g_Wt[3][2][HDim];
__device__ float g_v1[3][NHEAD][EDim];
__device__ float g_v2[3][EDim];
__device__ float g_edl1[3][NHEAD];
__device__ float g_edl2[3];
__device__ float g_easum[3][EDim];

// ---------------- setup -------------------------------------------------------
__global__ void k_zero_easum() {
    int t = threadIdx.x;
    if (t < 24) ((float*)g_easum)[t] = 0.f;
}

__global__ void k_easum(const float* __restrict__ ea0, const float* __restrict__ ea1,
                        const float* __restrict__ ea2) {
    const float* ea = blockIdx.y == 0 ? ea0 : (blockIdx.y == 1 ? ea1 : ea2);
    __shared__ float s[EDim];
    if (threadIdx.x < EDim) s[threadIdx.x] = 0.f;
    __syncthreads();
    float loc[EDim];
#pragma unroll
    for (int k = 0; k < EDim; k++) loc[k] = 0.f;
    int base = blockIdx.x * 4096;
    int lim = base + 4096; if (lim > Ee) lim = Ee;
    for (int e = base + threadIdx.x; e < lim; e += 256) {
        const float4* p = (const float4*)(ea + (size_t)e * 8);
        float4 a = p[0], b = p[1];
        loc[0] += a.x; loc[1] += a.y; loc[2] += a.z; loc[3] += a.w;
        loc[4] += b.x; loc[5] += b.y; loc[6] += b.z; loc[7] += b.w;
    }
#pragma unroll
    for (int k = 0; k < EDim; k++) atomicAdd(&s[k], loc[k]);
    __syncthreads();
    if (threadIdx.x < EDim) atomicAdd(&g_easum[blockIdx.y][threadIdx.x], s[threadIdx.x]);
}

__global__ void k_setup(const float* __restrict__ temb, const float* __restrict__ etg,
                        const float* __restrict__ eta, const float* __restrict__ W1,
                        const float* __restrict__ We1, const float* __restrict__ ae1,
                        const float* __restrict__ We2, const float* __restrict__ ae2) {
    int t = threadIdx.x;
    if (t < 3) g_gate[t] = 1.f / (1.f + __expf(-etg[t]));
    if (t == 0) {
        float m = fmaxf(eta[0], fmaxf(eta[1], eta[2]));
        float e0 = __expf(eta[0] - m), e1 = __expf(eta[1] - m), e2 = __expf(eta[2] - m);
        float s = e0 + e1 + e2;
        g_wts[0] = e0 / s; g_wts[1] = e1 / s; g_wts[2] = e2 / s;
    }
    __syncthreads();
    for (int idx = t; idx < 3 * 2 * HDim; idx += 256) {
        int i = idx / (2 * HDim); int r = idx % (2 * HDim);
        int ty = r / HDim; int j = r % HDim;
        float s = 0.f;
        for (int k = 0; k < 32; k++)
            s += temb[ty * 32 + k] * W1[i * 41 * HDim + (9 + k) * HDim + j];
        g_Wt[i][ty][j] = s;
    }
    for (int idx = t; idx < 3 * NHEAD * EDim; idx += 256) {
        int i = idx / 32; int h = (idx % 32) / 8; int k = idx % 8;
        float s = 0.f;
        for (int c = 0; c < 32; c++)
            s += We1[i * EDim * HDim + k * HDim + h * 32 + c] * ae1[i * NHEAD * 32 + h * 32 + c];
        g_v1[i][h][k] = g_gate[i] * s;
    }
    for (int idx = t; idx < 3 * EDim; idx += 256) {
        int i = idx / 8; int k = idx % 8;
        float s = 0.f;
        for (int c = 0; c < HDim; c++)
            s += We2[i * EDim * HDim + k * HDim + c] * ae2[i * HDim + c];
        g_v2[i][k] = g_gate[i] * s;
    }
    __syncthreads();
    if (t < 12) {
        int i = t / 4, h = t % 4;
        float s = 0.f;
        for (int k = 0; k < EDim; k++) s += (g_easum[i][k] / (float)Ee) * g_v1[i][h][k];
        g_edl1[i][h] = s;
    }
    if (t >= 32 && t < 35) {
        int i = t - 32;
        float s = 0.f;
        for (int k = 0; k < EDim; k++) s += (g_easum[i][k] / (float)Ee) * g_v2[i][k];
        g_edl2[i] = s;
    }
}

// ---------------- CSR build ----------------------------------------------------
__global__ void k_zero_deg() {
    int i = blockIdx.x * 256 + threadIdx.x;
    if (i < Nn) g_deg[i] = 0;
}

__global__ void k_deg(const int* __restrict__ ei) {
    int e = blockIdx.x * 1024 + threadIdx.x;
    if (e < Ee) atomicAdd(&g_deg[ei[Ee + e]], 1);
}

__global__ void k_partial() {
    __shared__ int s[512];
    int t = threadIdx.x;
    int i = blockIdx.x * 512 + t;
    s[t] = (i < Nn) ? g_deg[i] : 0;
    __syncthreads();
    for (int off = 256; off > 0; off >>= 1) {
        if (t < off) s[t] += s[t + off];
        __syncthreads();
    }
    if (t == 0) g_bsum[blockIdx.x] = s[0];
}

__global__ void k_scanb() {
    if (threadIdx.x == 0) {
        int s = 0;
        for (int b = 0; b < NCHUNK; b++) { int v = g_bsum[b]; g_bsum[b] = s; s += v; }
    }
}

__global__ void k_scan2() {
    __shared__ int s[512];
    int t = threadIdx.x;
    int i = blockIdx.x * 512 + t;
    int v = (i < Nn) ? g_deg[i] : 0;
    s[t] = v;
    __syncthreads();
    for (int off = 1; off < 512; off <<= 1) {
        int x = 0;
        if (t >= off) x = s[t - off];
        __syncthreads();
        s[t] += x;
        __syncthreads();
    }
    int excl = s[t] - v + g_bsum[blockIdx.x];
    if (i < Nn) {
        g_rowptr[i] = excl;
        g_cursor[i] = excl;
        if (i == Nn - 1) g_rowptr[Nn] = excl + v;
    }
}

__global__ void k_fill(const int* __restrict__ ei) {
    int e = blockIdx.x * 1024 + threadIdx.x;
    if (e >= Ee) return;
    int src = ei[e], dst = ei[Ee + e];
    int pos = atomicAdd(&g_cursor[dst], 1);
    g_csr_src[pos] = src;
    g_csr_eid[pos] = e;
}

// per-edge attention edge-term dots (both layers, one pass over ea)
__global__ void k_edot(const float* __restrict__ ea, int i) {
    int e = blockIdx.x * 256 + threadIdx.x;
    if (e >= Ee) return;
    const float4* p = (const float4*)(ea + (size_t)e * 8);
    float4 a0 = p[0], a1 = p[1];
    float4 d1;
    {
        const float* v = g_v1[i][0];
        d1.x = a0.x * v[0] + a0.y * v[1] + a0.z * v[2] + a0.w * v[3]
             + a1.x * v[4] + a1.y * v[5] + a1.z * v[6] + a1.w * v[7];
    }
    {
        const float* v = g_v1[i][1];
        d1.y = a0.x * v[0] + a0.y * v[1] + a0.z * v[2] + a0.w * v[3]
             + a1.x * v[4] + a1.y * v[5] + a1.z * v[6] + a1.w * v[7];
    }
    {
        const float* v = g_v1[i][2];
        d1.z = a0.x * v[0] + a0.y * v[1] + a0.z * v[2] + a0.w * v[3]
             + a1.x * v[4] + a1.y * v[5] + a1.z * v[6] + a1.w * v[7];
    }
    {
        const float* v = g_v1[i][3];
        d1.w = a0.x * v[0] + a0.y * v[1] + a0.z * v[2] + a0.w * v[3]
             + a1.x * v[4] + a1.y * v[5] + a1.z * v[6] + a1.w * v[7];
    }
    ((float4*)g_edot1)[e] = d1;
    const float* v = g_v2[i];
    g_edot2[e] = a0.x * v[0] + a0.y * v[1] + a0.z * v[2] + a0.w * v[3]
               + a1.x * v[4] + a1.y * v[5] + a1.z * v[6] + a1.w * v[7];
}

// ---------------- layer 1 projection + per-node attn logits + aloop ------------
__global__ void k_proj1(const float* __restrict__ nf, const int* __restrict__ ntype,
                        const float* __restrict__ W1i, const float* __restrict__ as1,
                        const float* __restrict__ ad1, int i) {
    int j = threadIdx.x; int h = j >> 5;
    float w[9];
#pragma unroll
    for (int k = 0; k < 9; k++) w[k] = W1i[k * HDim + j];
    float wt0 = g_Wt[i][0][j], wt1 = g_Wt[i][1][j];
    float as = as1[j], ad = ad1[j];
    int nb = blockIdx.x * 4;
#pragma unroll
    for (int nn = 0; nn < 4; nn++) {
        int n = nb + nn;
        const float* row = nf + (size_t)n * 9;
        float acc = ntype[n] ? wt1 : wt0;
#pragma unroll
        for (int k = 0; k < 9; k++) acc += row[k] * w[k];
        g_h[(size_t)n * HDim + j] = acc;
        float ss = acc * as, sd = acc * ad;
#pragma unroll
        for (int o = 16; o > 0; o >>= 1) {
            ss += __shfl_xor_sync(0xffffffffu, ss, o);
            sd += __shfl_xor_sync(0xffffffffu, sd, o);
        }
        if ((j & 31) == 0) {
            g_ssrc[n * NHEAD + h] = ss;
            g_sdst[n * NHEAD + h] = sd;
            float a = ss + sd + g_edl1[i][h];
            a = a > 0.f ? a : 0.2f * a;
            g_aloop[n * NHEAD + h] = a;
        }
    }
}

// ---------------- fused CSR gather (softmax-shifted by self-loop logit) --------
// MODE 1: write g_x2 = elu(out + b)        (layer 1)
// MODE 2: g_acc (=|+=) wts[i]*(out + b)    (layer 2)
template <int HH, int MODE>
__global__ void k_gather(const float* __restrict__ b, int i, int first) {
    int warp = threadIdx.x >> 5;
    int n = blockIdx.x * 8 + warp;
    if (n >= Nn) return;
    int lane = threadIdx.x & 31;
    int hh = (HH == 4) ? (lane >> 3) : 0;

    float sd_l = (lane < HH) ? g_sdst[n * HH + lane] : 0.f;
    float al_l = (lane < HH) ? g_aloop[n * HH + lane] : 0.f;
    float sdv = __shfl_sync(0xffffffffu, sd_l, hh);
    float alv = __shfl_sync(0xffffffffu, al_l, hh);

    float4 acc = ((const float4*)(g_h + (size_t)n * HDim))[lane];  // self loop, e=1
    float den = 1.f;

    int k = g_rowptr[n];
    int end = g_rowptr[n + 1];
    int src = 0, eid = 0;
    if (k < end) { src = g_csr_src[k]; eid = g_csr_eid[k]; }
    while (k < end) {
        int nsrc = 0, neid = 0;
        if (k + 1 < end) { nsrc = g_csr_src[k + 1]; neid = g_csr_eid[k + 1]; }
        float ss = g_ssrc[src * HH + hh];
        float ed = (HH == 4) ? g_edot1[(size_t)eid * 4 + hh] : g_edot2[eid];
        float a = ss + sdv + ed;
        a = a > 0.f ? a : 0.2f * a;
        float e = __expf(a - alv);
        den += e;
        float4 hv = ((const float4*)(g_h + (size_t)src * HDim))[lane];
        acc.x += e * hv.x; acc.y += e * hv.y; acc.z += e * hv.z; acc.w += e * hv.w;
        src = nsrc; eid = neid; k++;
    }

    float inv = 1.f / (den + 1e-16f);
    float4 bv = ((const float4*)b)[lane];
    float4 v;
    v.x = acc.x * inv + bv.x;
    v.y = acc.y * inv + bv.y;
    v.z = acc.z * inv + bv.z;
    v.w = acc.w * inv + bv.w;
    if (MODE == 1) {
        v.x = v.x > 0.f ? v.x : (expf(v.x) - 1.f);
        v.y = v.y > 0.f ? v.y : (expf(v.y) - 1.f);
        v.z = v.z > 0.f ? v.z : (expf(v.z) - 1.f);
        v.w = v.w > 0.f ? v.w : (expf(v.w) - 1.f);
        ((float4*)(g_x2 + (size_t)n * HDim))[lane] = v;
    } else {
        float w = g_wts[i];
        v.x *= w; v.y *= w; v.z *= w; v.w *= w;
        float4* dst = (float4*)(g_acc + (size_t)n * HDim) + lane;
        if (!first) {
            float4 o = *dst;
            v.x += o.x; v.y += o.y; v.z += o.z; v.w += o.w;
        }
        *dst = v;
    }
}

// ---------------- 128-wide SGEMM: g_h = g_x2 @ W ------------------------------
__global__ void gemm128(const float* __restrict__ W) {
    __shared__ __align__(16) float Xs[32][68];
    __shared__ __align__(16) float Ws[32][128];
    int tid = threadIdx.x;
    int ty = tid >> 4;
    int tx = tid & 15;
    int nb = blockIdx.x * 64;
    float acc[4][8];
#pragma unroll
    for (int q = 0; q < 4; q++)
#pragma unroll
        for (int p = 0; p < 8; p++) acc[q][p] = 0.f;

    for (int kt = 0; kt < 4; kt++) {
#pragma unroll
        for (int i = 0; i < 8; i++) {
            int el = tid + i * 256;
            int nn = el >> 5; int kk = el & 31;
            int n = nb + nn;
            Xs[kk][nn] = (n < Nn) ? g_x2[(size_t)n * 128 + kt * 32 + kk] : 0.f;
        }
#pragma unroll
        for (int i = 0; i < 16; i++) {
            int el = tid + i * 256;
            int kk = el >> 7; int j = el & 127;
            Ws[kk][j] = W[(kt * 32 + kk) * 128 + j];
        }
        __syncthreads();
#pragma unroll
        for (int kk = 0; kk < 32; kk++) {
            float4 xv = *(const float4*)&Xs[kk][ty * 4];
            float4 w0 = *(const float4*)&Ws[kk][tx * 8];
            float4 w1 = *(const float4*)&Ws[kk][tx * 8 + 4];
            float xq[4] = {xv.x, xv.y, xv.z, xv.w};
            float wq[8] = {w0.x, w0.y, w0.z, w0.w, w1.x, w1.y, w1.z, w1.w};
#pragma unroll
            for (int q = 0; q < 4; q++)
#pragma unroll
                for (int p = 0; p < 8; p++) acc[q][p] += xq[q] * wq[p];
        }
        __syncthreads();
    }
#pragma unroll
    for (int q = 0; q < 4; q++) {
        int n = nb + ty * 4 + q;
        if (n < Nn) {
            float4 o0 = make_float4(acc[q][0], acc[q][1], acc[q][2], acc[q][3]);
            float4 o1 = make_float4(acc[q][4], acc[q][5], acc[q][6], acc[q][7]);
            *(float4*)&g_h[(size_t)n * 128 + tx * 8] = o0;
            *(float4*)&g_h[(size_t)n * 128 + tx * 8 + 4] = o1;
        }
    }
}

// layer-2 per-node logits + aloop
__global__ void k_s2(const float* __restrict__ as2, const float* __restrict__ ad2, int i) {
    int n = blockIdx.x * 8 + (threadIdx.x >> 5);
    if (n >= Nn) return;
    int lane = threadIdx.x & 31;
    float ss = 0.f, sd = 0.f;
#pragma unroll
    for (int k = 0; k < 4; k++) {
        int j = lane + k * 32;
        float hv = g_h[(size_t)n * HDim + j];
        ss += hv * as2[j]; sd += hv * ad2[j];
    }
#pragma unroll
    for (int o = 16; o > 0; o >>= 1) {
        ss += __shfl_xor_sync(0xffffffffu, ss, o);
        sd += __shfl_xor_sync(0xffffffffu, sd, o);
    }
    if (lane == 0) {
        g_ssrc[n] = ss; g_sdst[n] = sd;
        float a = ss + sd + g_edl2[i];
        a = a > 0.f ? a : 0.2f * a;
        g_aloop[n] = a;
    }
}

// ---------------- pooling / readout -------------------------------------------
__global__ void k_scores(const float* __restrict__ pW, const float* __restrict__ pb) {
    int v = blockIdx.x * 8 + (threadIdx.x >> 5);
    if (v >= Vv) return;
    int lane = threadIdx.x & 31;
    float s = 0.f;
#pragma unroll
    for (int k = 0; k < 4; k++) {
        int j = lane + k * 32;
        s += g_acc[(size_t)(Rr + v) * HDim + j] * pW[j];
    }
#pragma unroll
    for (int o = 16; o > 0; o >>= 1) s += __shfl_xor_sync(0xffffffffu, s, o);
    if (lane == 0) g_scores[v] = s + pb[0];
}

__global__ void k_stats(const int* __restrict__ mask) {
    int r = blockIdx.x; int t = threadIdx.x;
    __shared__ float red[256];
    __shared__ int redi[256];
    const int* mrow = mask + (size_t)r * Vv;
    float mx = -3.0e38f;
    for (int v = t; v < Vv; v += 256) if (mrow[v]) mx = fmaxf(mx, g_scores[v]);
    red[t] = mx; __syncthreads();
    for (int s = 128; s > 0; s >>= 1) { if (t < s) red[t] = fmaxf(red[t], red[t + s]); __syncthreads(); }
    float m = red[0]; __syncthreads();
    float sm = 0.f; int c = 0;
    for (int v = t; v < Vv; v += 256)
        if (mrow[v]) { sm += __expf(g_scores[v] - m); c++; }
    red[t] = sm; redi[t] = c; __syncthreads();
    for (int s = 128; s > 0; s >>= 1) {
        if (t < s) { red[t] += red[t + s]; redi[t] += redi[t + s]; }
        __syncthreads();
    }
    if (t == 0) { g_pmax[r] = m; g_pden[r] = red[0]; g_pcnt[r] = redi[0]; }
    if (t < HDim) g_pooled[r * HDim + t] = 0.f;
}

// fused: compute attention weights inline and accumulate pooled = aw @ veh
__global__ void k_pooled(const int* __restrict__ mask) {
    __shared__ float aws[64 * 128];
    int t = threadIdx.x;
    int vb = blockIdx.x * 128;
    int nv = Vv - vb; if (nv > 128) nv = 128;
    for (int idx = t; idx < 64 * 128; idx += 256) {
        int r = idx >> 7, v = idx & 127;
        float aw = 0.f;
        if (v < nv) {
            int mv = mask[(size_t)r * Vv + vb + v];
            if (mv && g_pcnt[r] > 0)
                aw = __expf(g_scores[vb + v] - g_pmax[r]) / g_pden[r];
        }
        aws[idx] = aw;
    }
    __syncthreads();
    int rg = t >> 7, c = t & 127;
    float acc[32];
#pragma unroll
    for (int rr = 0; rr < 32; rr++) acc[rr] = 0.f;
    for (int v = 0; v < nv; v++) {
        float vx = g_acc[(size_t)(Rr + vb + v) * HDim + c];
#pragma unroll
        for (int rr = 0; rr < 32; rr++) acc[rr] += aws[(rg * 32 + rr) * 128 + v] * vx;
    }
    for (int rr = 0; rr < 32; rr++)
        atomicAdd(&g_pooled[(rg * 32 + rr) * 128 + c], acc[rr]);
}

__global__ void k_q1(const float* __restrict__ Wo1, const float* __restrict__ bo1) {
    __shared__ float comb[256];
    int r = blockIdx.x, t = threadIdx.x;
    comb[t] = g_acc[r * HDim + t];
    comb[128 + t] = g_pooled[r * HDim + t];
    __syncthreads();
    float a = bo1[t];
    for (int k = 0; k < 256; k++) a += comb[k] * Wo1[k * 128 + t];
    g_q1[r * 128 + t] = fmaxf(a, 0.f);
}

__global__ void k_q2(const float* __restrict__ Wo2, const float* __restrict__ bo2) {
    __shared__ float q[128];
    int r = blockIdx.x, t = threadIdx.x;
    q[t] = g_q1[r * 128 + t]; q[64 + t] = g_q1[r * 128 + 64 + t];
    __syncthreads();
    float a = bo2[t];
    for (int k = 0; k < 128; k++) a += q[k] * Wo2[k * 64 + t];
    g_q2[r * 64 + t] = fmaxf(a, 0.f);
}

__global__ void k_q3(const float* __restrict__ Wo3, const float* __restrict__ bo3,
                     const float* __restrict__ eta, float* __restrict__ out, int out_size) {
    __shared__ float q[64];
    int r = blockIdx.x, t = threadIdx.x;
    q[t] = g_q2[r * 64 + t]; q[32 + t] = g_q2[r * 64 + 32 + t];
    __syncthreads();
    if (t < 16) {
        float a = bo3[t];
        for (int k = 0; k < 64; k++) a += q[k] * Wo3[k * 16 + t];
        int oi = r * 16 + t;
        if (oi < out_size) out[oi] = a;
    }
    if (r == 0 && t >= 16 && t < 19) {
        int oi = 1024 + (t - 16);
        if (oi < out_size) out[oi] = eta[t - 16];
    }
}

// ---------------- launch --------------------------------------------------------
extern "C" void kernel_launch(void* const* d_in, const int* in_sizes, int n_in,
                              void* d_out, int out_size) {
    const float* nf    = (const float*)d_in[0];
    const float* eaA[3] = {(const float*)d_in[1], (const float*)d_in[2], (const float*)d_in[3]};
    const float* temb  = (const float*)d_in[4];
    const float* etg   = (const float*)d_in[5];
    const float* eta   = (const float*)d_in[6];
    const float* W1    = (const float*)d_in[7];
    const float* as1   = (const float*)d_in[8];
    const float* ad1   = (const float*)d_in[9];
    const float* We1   = (const float*)d_in[10];
    const float* ae1   = (const float*)d_in[11];
    const float* b1    = (const float*)d_in[12];
    const float* W2    = (const float*)d_in[13];
    const float* as2   = (const float*)d_in[14];
    const float* ad2   = (const float*)d_in[15];
    const float* We2   = (const float*)d_in[16];
    const float* ae2   = (const float*)d_in[17];
    const float* b2    = (const float*)d_in[18];
    const float* pW    = (const float*)d_in[19];
    const float* pb    = (const float*)d_in[20];
    const float* Wo1   = (const float*)d_in[21];
    const float* bo1   = (const float*)d_in[22];
    const float* Wo2   = (const float*)d_in[23];
    const float* bo2   = (const float*)d_in[24];
    const float* Wo3   = (const float*)d_in[25];
    const float* bo3   = (const float*)d_in[26];
    const int* ntype   = (const int*)d_in[27];
    const int* eiA[3]  = {(const int*)d_in[28], (const int*)d_in[29], (const int*)d_in[30]};
    const int* mask    = (const int*)d_in[31];
    float* out = (float*)d_out;

    k_zero_easum<<<1, 32>>>();
    { dim3 g(147, 3); k_easum<<<g, 256>>>(eaA[0], eaA[1], eaA[2]); }
    k_setup<<<1, 256>>>(temb, etg, eta, W1, We1, ae1, We2, ae2);

    for (int i = 0; i < 3; i++) {
        // CSR build for this edge type
        k_zero_deg<<<196, 256>>>();
        k_deg<<<586, 1024>>>(eiA[i]);
        k_partial<<<NCHUNK, 512>>>();
        k_scanb<<<1, 32>>>();
        k_scan2<<<NCHUNK, 512>>>();
        k_fill<<<586, 1024>>>(eiA[i]);
        k_edot<<<2344, 256>>>(eaA[i], i);

        // layer 1
        k_proj1<<<12500, 128>>>(nf, ntype, W1 + i * 41 * 128, as1 + i * 128, ad1 + i * 128, i);
        k_gather<4, 1><<<6250, 256>>>(b1 + i * 128, i, 0);
        // layer 2
        gemm128<<<782, 256>>>(W2 + i * 128 * 128);
        k_s2<<<6250, 256>>>(as2 + i * 128, ad2 + i * 128, i);
        k_gather<1, 2><<<6250, 256>>>(b2 + i * 128, i, i == 0 ? 1 : 0);
    }

    k_scores<<<6242, 256>>>(pW, pb);
    k_stats<<<64, 256>>>(mask);
    k_pooled<<<391, 256>>>(mask);
    k_q1<<<64, 128>>>(Wo1, bo1);
    k_q2<<<64, 64>>>(Wo2, bo2);
    k_q3<<<64, 32>>>(Wo3, bo3, eta, out, out_size);
}

// round 4
// speedup vs baseline: 1.7174x; 1.0985x over previous
#include <cuda_runtime.h>
#include <math.h>

#define Nn 50000
#define Ee 600000
#define Rr 64
#define Vv 49936
#define HDim 128
#define NHEAD 4
#define EDim 8
#define NCHUNK 98   // ceil(50000/512)

// ---------------- scratch (__device__ globals; no cudaMalloc) ---------------
__device__ float g_h[3][(size_t)Nn * HDim];
__device__ float g_x2[3][(size_t)Nn * HDim];
__device__ float g_acc[(size_t)Nn * HDim];
__device__ float g_ssrc[3][Nn * NHEAD];
__device__ float g_sdst[3][Nn * NHEAD];
__device__ float g_aloop[3][Nn * NHEAD];
__device__ int   g_deg[3][Nn];
__device__ int   g_cursor[3][Nn];
__device__ int   g_rowptr[3][Nn + 1];
__device__ int   g_bsum[3][NCHUNK];
__device__ int   g_csr_src[3][Ee];
__device__ int   g_csr_eid[3][Ee];
__device__ float g_edot1[3][(size_t)Ee * 4];
__device__ float g_edot2[3][Ee];
__device__ float g_scores[Vv];
__device__ float g_pmax[Rr], g_pden[Rr];
__device__ int   g_pcnt[Rr];
__device__ float g_pooled[Rr * HDim];
__device__ float g_q1[Rr * HDim];
__device__ float g_q2[Rr * 64];
__device__ float g_gate[3], g_wts[3];
__device__ float g_Wt[3][2][HDim];
__device__ float g_v1[3][NHEAD][EDim];
__device__ float g_v2[3][EDim];
__device__ float g_edl1[3][NHEAD];
__device__ float g_edl2[3];
__device__ float g_easum[3][EDim];

// ---------------- setup -------------------------------------------------------
__global__ void k_zero_easum() {
    int t = threadIdx.x;
    if (t < 24) ((float*)g_easum)[t] = 0.f;
}

__global__ void k_easum(const float* __restrict__ ea0, const float* __restrict__ ea1,
                        const float* __restrict__ ea2) {
    const float* ea = blockIdx.y == 0 ? ea0 : (blockIdx.y == 1 ? ea1 : ea2);
    __shared__ float s[EDim];
    if (threadIdx.x < EDim) s[threadIdx.x] = 0.f;
    __syncthreads();
    float loc[EDim];
#pragma unroll
    for (int k = 0; k < EDim; k++) loc[k] = 0.f;
    int base = blockIdx.x * 4096;
    int lim = base + 4096; if (lim > Ee) lim = Ee;
    for (int e = base + threadIdx.x; e < lim; e += 256) {
        const float4* p = (const float4*)(ea + (size_t)e * 8);
        float4 a = p[0], b = p[1];
        loc[0] += a.x; loc[1] += a.y; loc[2] += a.z; loc[3] += a.w;
        loc[4] += b.x; loc[5] += b.y; loc[6] += b.z; loc[7] += b.w;
    }
#pragma unroll
    for (int k = 0; k < EDim; k++) atomicAdd(&s[k], loc[k]);
    __syncthreads();
    if (threadIdx.x < EDim) atomicAdd(&g_easum[blockIdx.y][threadIdx.x], s[threadIdx.x]);
}

__global__ void k_setup(const float* __restrict__ temb, const float* __restrict__ etg,
                        const float* __restrict__ eta, const float* __restrict__ W1,
                        const float* __restrict__ We1, const float* __restrict__ ae1,
                        const float* __restrict__ We2, const float* __restrict__ ae2) {
    int t = threadIdx.x;
    if (t < 3) g_gate[t] = 1.f / (1.f + __expf(-etg[t]));
    if (t == 0) {
        float m = fmaxf(eta[0], fmaxf(eta[1], eta[2]));
        float e0 = __expf(eta[0] - m), e1 = __expf(eta[1] - m), e2 = __expf(eta[2] - m);
        float s = e0 + e1 + e2;
        g_wts[0] = e0 / s; g_wts[1] = e1 / s; g_wts[2] = e2 / s;
    }
    __syncthreads();
    for (int idx = t; idx < 3 * 2 * HDim; idx += 256) {
        int i = idx / (2 * HDim); int r = idx % (2 * HDim);
        int ty = r / HDim; int j = r % HDim;
        float s = 0.f;
        for (int k = 0; k < 32; k++)
            s += temb[ty * 32 + k] * W1[i * 41 * HDim + (9 + k) * HDim + j];
        g_Wt[i][ty][j] = s;
    }
    for (int idx = t; idx < 3 * NHEAD * EDim; idx += 256) {
        int i = idx / 32; int h = (idx % 32) / 8; int k = idx % 8;
        float s = 0.f;
        for (int c = 0; c < 32; c++)
            s += We1[i * EDim * HDim + k * HDim + h * 32 + c] * ae1[i * NHEAD * 32 + h * 32 + c];
        g_v1[i][h][k] = g_gate[i] * s;
    }
    for (int idx = t; idx < 3 * EDim; idx += 256) {
        int i = idx / 8; int k = idx % 8;
        float s = 0.f;
        for (int c = 0; c < HDim; c++)
            s += We2[i * EDim * HDim + k * HDim + c] * ae2[i * HDim + c];
        g_v2[i][k] = g_gate[i] * s;
    }
    __syncthreads();
    if (t < 12) {
        int i = t / 4, h = t % 4;
        float s = 0.f;
        for (int k = 0; k < EDim; k++) s += (g_easum[i][k] / (float)Ee) * g_v1[i][h][k];
        g_edl1[i][h] = s;
    }
    if (t >= 32 && t < 35) {
        int i = t - 32;
        float s = 0.f;
        for (int k = 0; k < EDim; k++) s += (g_easum[i][k] / (float)Ee) * g_v2[i][k];
        g_edl2[i] = s;
    }
}

// ---------------- CSR build (batched over 3 types via grid.y) ------------------
__global__ void k_zero_deg() {
    int i = blockIdx.x * 256 + threadIdx.x;
    if (i < 3 * Nn) ((int*)g_deg)[i] = 0;
}

__global__ void k_deg(const int* __restrict__ ei0, const int* __restrict__ ei1,
                      const int* __restrict__ ei2) {
    const int* ei = blockIdx.y == 0 ? ei0 : (blockIdx.y == 1 ? ei1 : ei2);
    int e = blockIdx.x * 1024 + threadIdx.x;
    if (e < Ee) atomicAdd(&g_deg[blockIdx.y][ei[Ee + e]], 1);
}

__global__ void k_partial() {
    __shared__ int s[512];
    int ty = blockIdx.y;
    int t = threadIdx.x;
    int i = blockIdx.x * 512 + t;
    s[t] = (i < Nn) ? g_deg[ty][i] : 0;
    __syncthreads();
    for (int off = 256; off > 0; off >>= 1) {
        if (t < off) s[t] += s[t + off];
        __syncthreads();
    }
    if (t == 0) g_bsum[ty][blockIdx.x] = s[0];
}

__global__ void k_scanb() {
    int t = threadIdx.x;
    if (t < 3) {
        int s = 0;
        for (int b = 0; b < NCHUNK; b++) { int v = g_bsum[t][b]; g_bsum[t][b] = s; s += v; }
    }
}

__global__ void k_scan2() {
    __shared__ int s[512];
    int ty = blockIdx.y;
    int t = threadIdx.x;
    int i = blockIdx.x * 512 + t;
    int v = (i < Nn) ? g_deg[ty][i] : 0;
    s[t] = v;
    __syncthreads();
    for (int off = 1; off < 512; off <<= 1) {
        int x = 0;
        if (t >= off) x = s[t - off];
        __syncthreads();
        s[t] += x;
        __syncthreads();
    }
    int excl = s[t] - v + g_bsum[ty][blockIdx.x];
    if (i < Nn) {
        g_rowptr[ty][i] = excl;
        g_cursor[ty][i] = excl;
        if (i == Nn - 1) g_rowptr[ty][Nn] = excl + v;
    }
}

__global__ void k_fill(const int* __restrict__ ei0, const int* __restrict__ ei1,
                       const int* __restrict__ ei2) {
    int ty = blockIdx.y;
    const int* ei = ty == 0 ? ei0 : (ty == 1 ? ei1 : ei2);
    int e = blockIdx.x * 1024 + threadIdx.x;
    if (e >= Ee) return;
    int src = ei[e], dst = ei[Ee + e];
    int pos = atomicAdd(&g_cursor[ty][dst], 1);
    g_csr_src[ty][pos] = src;
    g_csr_eid[ty][pos] = e;
}

// per-edge attention edge-term dots (both layers, batched)
__global__ void k_edot(const float* __restrict__ ea0, const float* __restrict__ ea1,
                       const float* __restrict__ ea2) {
    int i = blockIdx.y;
    const float* ea = i == 0 ? ea0 : (i == 1 ? ea1 : ea2);
    int e = blockIdx.x * 256 + threadIdx.x;
    if (e >= Ee) return;
    const float4* p = (const float4*)(ea + (size_t)e * 8);
    float4 a0 = p[0], a1 = p[1];
    float4 d1;
    {
        const float* v = g_v1[i][0];
        d1.x = a0.x * v[0] + a0.y * v[1] + a0.z * v[2] + a0.w * v[3]
             + a1.x * v[4] + a1.y * v[5] + a1.z * v[6] + a1.w * v[7];
    }
    {
        const float* v = g_v1[i][1];
        d1.y = a0.x * v[0] + a0.y * v[1] + a0.z * v[2] + a0.w * v[3]
             + a1.x * v[4] + a1.y * v[5] + a1.z * v[6] + a1.w * v[7];
    }
    {
        const float* v = g_v1[i][2];
        d1.z = a0.x * v[0] + a0.y * v[1] + a0.z * v[2] + a0.w * v[3]
             + a1.x * v[4] + a1.y * v[5] + a1.z * v[6] + a1.w * v[7];
    }
    {
        const float* v = g_v1[i][3];
        d1.w = a0.x * v[0] + a0.y * v[1] + a0.z * v[2] + a0.w * v[3]
             + a1.x * v[4] + a1.y * v[5] + a1.z * v[6] + a1.w * v[7];
    }
    ((float4*)g_edot1[i])[e] = d1;
    const float* v = g_v2[i];
    g_edot2[i][e] = a0.x * v[0] + a0.y * v[1] + a0.z * v[2] + a0.w * v[3]
                  + a1.x * v[4] + a1.y * v[5] + a1.z * v[6] + a1.w * v[7];
}

// ---------------- layer 1 projection + per-node attn logits + aloop ------------
__global__ void k_proj1(const float* __restrict__ nf, const int* __restrict__ ntype,
                        const float* __restrict__ W1, const float* __restrict__ as1,
                        const float* __restrict__ ad1) {
    int i = blockIdx.y;
    const float* W1i = W1 + (size_t)i * 41 * HDim;
    int j = threadIdx.x; int h = j >> 5;
    float w[9];
#pragma unroll
    for (int k = 0; k < 9; k++) w[k] = W1i[k * HDim + j];
    float wt0 = g_Wt[i][0][j], wt1 = g_Wt[i][1][j];
    float as = as1[i * HDim + j], ad = ad1[i * HDim + j];
    float* hout = g_h[i];
    int nb = blockIdx.x * 4;
#pragma unroll
    for (int nn = 0; nn < 4; nn++) {
        int n = nb + nn;
        const float* row = nf + (size_t)n * 9;
        float acc = ntype[n] ? wt1 : wt0;
#pragma unroll
        for (int k = 0; k < 9; k++) acc += row[k] * w[k];
        hout[(size_t)n * HDim + j] = acc;
        float ss = acc * as, sd = acc * ad;
#pragma unroll
        for (int o = 16; o > 0; o >>= 1) {
            ss += __shfl_xor_sync(0xffffffffu, ss, o);
            sd += __shfl_xor_sync(0xffffffffu, sd, o);
        }
        if ((j & 31) == 0) {
            g_ssrc[i][n * NHEAD + h] = ss;
            g_sdst[i][n * NHEAD + h] = sd;
            float a = ss + sd + g_edl1[i][h];
            a = a > 0.f ? a : 0.2f * a;
            g_aloop[i][n * NHEAD + h] = a;
        }
    }
}

// ---------------- fused CSR gather (softmax shifted by self-loop logit) --------
// MODE 1: g_x2[i] = elu(out + b)                 (layer 1, HH=4)
// MODE 2: g_x2[i] = wts[i]*(out + b)             (layer 2, HH=1; combined later)
template <int HH, int MODE>
__global__ void k_gather(const float* __restrict__ b) {
    int i = blockIdx.y;
    int warp = threadIdx.x >> 5;
    int n = blockIdx.x * 8 + warp;
    if (n >= Nn) return;
    int lane = threadIdx.x & 31;
    int hh = (HH == 4) ? (lane >> 3) : 0;

    const float* hbase = g_h[i];
    const float* ssrc = g_ssrc[i];
    const int* csrs = g_csr_src[i];
    const int* csre = g_csr_eid[i];
    const float* ed1 = g_edot1[i];
    const float* ed2 = g_edot2[i];

    float sdv = g_sdst[i][n * HH + hh];
    float alv = g_aloop[i][n * HH + hh];

    float4 acc = ((const float4*)(hbase + (size_t)n * HDim))[lane];  // self loop, e=1
    float den = 1.f;

    int k = g_rowptr[i][n];
    int end = g_rowptr[i][n + 1];
#pragma unroll 1
    for (; k + 1 < end; k += 2) {
        int s0 = csrs[k],     e0 = csre[k];
        int s1 = csrs[k + 1], e1 = csre[k + 1];
        float4 h0 = ((const float4*)(hbase + (size_t)s0 * HDim))[lane];
        float4 h1 = ((const float4*)(hbase + (size_t)s1 * HDim))[lane];
        float ss0 = ssrc[s0 * HH + hh];
        float ss1 = ssrc[s1 * HH + hh];
        float edv0 = (HH == 4) ? ed1[(size_t)e0 * 4 + hh] : ed2[e0];
        float edv1 = (HH == 4) ? ed1[(size_t)e1 * 4 + hh] : ed2[e1];
        float a0 = ss0 + sdv + edv0; a0 = a0 > 0.f ? a0 : 0.2f * a0;
        float a1 = ss1 + sdv + edv1; a1 = a1 > 0.f ? a1 : 0.2f * a1;
        float x0 = __expf(a0 - alv);
        float x1 = __expf(a1 - alv);
        den += x0 + x1;
        acc.x += x0 * h0.x + x1 * h1.x;
        acc.y += x0 * h0.y + x1 * h1.y;
        acc.z += x0 * h0.z + x1 * h1.z;
        acc.w += x0 * h0.w + x1 * h1.w;
    }
    if (k < end) {
        int s0 = csrs[k], e0 = csre[k];
        float4 h0 = ((const float4*)(hbase + (size_t)s0 * HDim))[lane];
        float ss0 = ssrc[s0 * HH + hh];
        float edv0 = (HH == 4) ? ed1[(size_t)e0 * 4 + hh] : ed2[e0];
        float a0 = ss0 + sdv + edv0; a0 = a0 > 0.f ? a0 : 0.2f * a0;
        float x0 = __expf(a0 - alv);
        den += x0;
        acc.x += x0 * h0.x; acc.y += x0 * h0.y; acc.z += x0 * h0.z; acc.w += x0 * h0.w;
    }

    float inv = 1.f / (den + 1e-16f);
    float4 bv = ((const float4*)(b + i * HDim))[lane];
    float4 v;
    v.x = acc.x * inv + bv.x;
    v.y = acc.y * inv + bv.y;
    v.z = acc.z * inv + bv.z;
    v.w = acc.w * inv + bv.w;
    if (MODE == 1) {
        v.x = v.x > 0.f ? v.x : (expf(v.x) - 1.f);
        v.y = v.y > 0.f ? v.y : (expf(v.y) - 1.f);
        v.z = v.z > 0.f ? v.z : (expf(v.z) - 1.f);
        v.w = v.w > 0.f ? v.w : (expf(v.w) - 1.f);
    } else {
        float w = g_wts[i];
        v.x *= w; v.y *= w; v.z *= w; v.w *= w;
    }
    ((float4*)(g_x2[i] + (size_t)n * HDim))[lane] = v;
}

// ---------------- 128-wide SGEMM: g_h[i] = g_x2[i] @ W2[i] ----------------------
__global__ void gemm128(const float* __restrict__ W2) {
    int ty = blockIdx.y;
    const float* X = g_x2[ty];
    float* Y = g_h[ty];
    const float* W = W2 + (size_t)ty * HDim * HDim;
    __shared__ __align__(16) float Xs[32][68];
    __shared__ __align__(16) float Ws[32][128];
    int tid = threadIdx.x;
    int tyy = tid >> 4;
    int tx = tid & 15;
    int nb = blockIdx.x * 64;
    float acc[4][8];
#pragma unroll
    for (int q = 0; q < 4; q++)
#pragma unroll
        for (int p = 0; p < 8; p++) acc[q][p] = 0.f;

    for (int kt = 0; kt < 4; kt++) {
#pragma unroll
        for (int i = 0; i < 8; i++) {
            int el = tid + i * 256;
            int nn = el >> 5; int kk = el & 31;
            int n = nb + nn;
            Xs[kk][nn] = (n < Nn) ? X[(size_t)n * 128 + kt * 32 + kk] : 0.f;
        }
#pragma unroll
        for (int i = 0; i < 16; i++) {
            int el = tid + i * 256;
            int kk = el >> 7; int j = el & 127;
            Ws[kk][j] = W[(kt * 32 + kk) * 128 + j];
        }
        __syncthreads();
#pragma unroll
        for (int kk = 0; kk < 32; kk++) {
            float4 xv = *(const float4*)&Xs[kk][tyy * 4];
            float4 w0 = *(const float4*)&Ws[kk][tx * 8];
            float4 w1 = *(const float4*)&Ws[kk][tx * 8 + 4];
            float xq[4] = {xv.x, xv.y, xv.z, xv.w};
            float wq[8] = {w0.x, w0.y, w0.z, w0.w, w1.x, w1.y, w1.z, w1.w};
#pragma unroll
            for (int q = 0; q < 4; q++)
#pragma unroll
                for (int p = 0; p < 8; p++) acc[q][p] += xq[q] * wq[p];
        }
        __syncthreads();
    }
#pragma unroll
    for (int q = 0; q < 4; q++) {
        int n = nb + tyy * 4 + q;
        if (n < Nn) {
            float4 o0 = make_float4(acc[q][0], acc[q][1], acc[q][2], acc[q][3]);
            float4 o1 = make_float4(acc[q][4], acc[q][5], acc[q][6], acc[q][7]);
            *(float4*)&Y[(size_t)n * 128 + tx * 8] = o0;
            *(float4*)&Y[(size_t)n * 128 + tx * 8 + 4] = o1;
        }
    }
}

// layer-2 per-node logits + aloop (batched)
__global__ void k_s2(const float* __restrict__ as2, const float* __restrict__ ad2) {
    int i = blockIdx.y;
    int n = blockIdx.x * 8 + (threadIdx.x >> 5);
    if (n >= Nn) return;
    int lane = threadIdx.x & 31;
    float ss = 0.f, sd = 0.f;
#pragma unroll
    for (int k = 0; k < 4; k++) {
        int j = lane + k * 32;
        float hv = g_h[i][(size_t)n * HDim + j];
        ss += hv * as2[i * HDim + j]; sd += hv * ad2[i * HDim + j];
    }
#pragma unroll
    for (int o = 16; o > 0; o >>= 1) {
        ss += __shfl_xor_sync(0xffffffffu, ss, o);
        sd += __shfl_xor_sync(0xffffffffu, sd, o);
    }
    if (lane == 0) {
        g_ssrc[i][n] = ss; g_sdst[i][n] = sd;
        float a = ss + sd + g_edl2[i];
        a = a > 0.f ? a : 0.2f * a;
        g_aloop[i][n] = a;
    }
}

// combine 3 weighted type outputs
__global__ void k_combine() {
    int idx = blockIdx.x * 256 + threadIdx.x;  // float4 index
    if (idx >= Nn * HDim / 4) return;
    float4 a = ((const float4*)g_x2[0])[idx];
    float4 b = ((const float4*)g_x2[1])[idx];
    float4 c = ((const float4*)g_x2[2])[idx];
    float4 v;
    v.x = a.x + b.x + c.x;
    v.y = a.y + b.y + c.y;
    v.z = a.z + b.z + c.z;
    v.w = a.w + b.w + c.w;
    ((float4*)g_acc)[idx] = v;
}

// ---------------- pooling / readout -------------------------------------------
__global__ void k_scores(const float* __restrict__ pW, const float* __restrict__ pb) {
    int v = blockIdx.x * 8 + (threadIdx.x >> 5);
    if (v >= Vv) return;
    int lane = threadIdx.x & 31;
    float s = 0.f;
#pragma unroll
    for (int k = 0; k < 4; k++) {
        int j = lane + k * 32;
        s += g_acc[(size_t)(Rr + v) * HDim + j] * pW[j];
    }
#pragma unroll
    for (int o = 16; o > 0; o >>= 1) s += __shfl_xor_sync(0xffffffffu, s, o);
    if (lane == 0) g_scores[v] = s + pb[0];
}

__global__ void k_stats(const int* __restrict__ mask) {
    int r = blockIdx.x; int t = threadIdx.x;
    __shared__ float red[256];
    __shared__ int redi[256];
    const int* mrow = mask + (size_t)r * Vv;
    float mx = -3.0e38f;
    for (int v = t; v < Vv; v += 256) if (mrow[v]) mx = fmaxf(mx, g_scores[v]);
    red[t] = mx; __syncthreads();
    for (int s = 128; s > 0; s >>= 1) { if (t < s) red[t] = fmaxf(red[t], red[t + s]); __syncthreads(); }
    float m = red[0]; __syncthreads();
    float sm = 0.f; int c = 0;
    for (int v = t; v < Vv; v += 256)
        if (mrow[v]) { sm += __expf(g_scores[v] - m); c++; }
    red[t] = sm; redi[t] = c; __syncthreads();
    for (int s = 128; s > 0; s >>= 1) {
        if (t < s) { red[t] += red[t + s]; redi[t] += redi[t + s]; }
        __syncthreads();
    }
    if (t == 0) { g_pmax[r] = m; g_pden[r] = red[0]; g_pcnt[r] = redi[0]; }
    if (t < HDim) g_pooled[r * HDim + t] = 0.f;
}

__global__ void k_pooled(const int* __restrict__ mask) {
    __shared__ float aws[64 * 128];
    int t = threadIdx.x;
    int vb = blockIdx.x * 128;
    int nv = Vv - vb; if (nv > 128) nv = 128;
    for (int idx = t; idx < 64 * 128; idx += 256) {
        int r = idx >> 7, v = idx & 127;
        float aw = 0.f;
        if (v < nv) {
            int mv = mask[(size_t)r * Vv + vb + v];
            if (mv && g_pcnt[r] > 0)
                aw = __expf(g_scores[vb + v] - g_pmax[r]) / g_pden[r];
        }
        aws[idx] = aw;
    }
    __syncthreads();
    int rg = t >> 7, c = t & 127;
    float acc[32];
#pragma unroll
    for (int rr = 0; rr < 32; rr++) acc[rr] = 0.f;
    for (int v = 0; v < nv; v++) {
        float vx = g_acc[(size_t)(Rr + vb + v) * HDim + c];
#pragma unroll
        for (int rr = 0; rr < 32; rr++) acc[rr] += aws[(rg * 32 + rr) * 128 + v] * vx;
    }
    for (int rr = 0; rr < 32; rr++)
        atomicAdd(&g_pooled[(rg * 32 + rr) * 128 + c], acc[rr]);
}

__global__ void k_q1(const float* __restrict__ Wo1, const float* __restrict__ bo1) {
    __shared__ float comb[256];
    int r = blockIdx.x, t = threadIdx.x;
    comb[t] = g_acc[r * HDim + t];
    comb[128 + t] = g_pooled[r * HDim + t];
    __syncthreads();
    float a = bo1[t];
    for (int k = 0; k < 256; k++) a += comb[k] * Wo1[k * 128 + t];
    g_q1[r * 128 + t] = fmaxf(a, 0.f);
}

__global__ void k_q2(const float* __restrict__ Wo2, const float* __restrict__ bo2) {
    __shared__ float q[128];
    int r = blockIdx.x, t = threadIdx.x;
    q[t] = g_q1[r * 128 + t]; q[64 + t] = g_q1[r * 128 + 64 + t];
    __syncthreads();
    float a = bo2[t];
    for (int k = 0; k < 128; k++) a += q[k] * Wo2[k * 64 + t];
    g_q2[r * 64 + t] = fmaxf(a, 0.f);
}

__global__ void k_q3(const float* __restrict__ Wo3, const float* __restrict__ bo3,
                     const float* __restrict__ eta, float* __restrict__ out, int out_size) {
    __shared__ float q[64];
    int r = blockIdx.x, t = threadIdx.x;
    q[t] = g_q2[r * 64 + t]; q[32 + t] = g_q2[r * 64 + 32 + t];
    __syncthreads();
    if (t < 16) {
        float a = bo3[t];
        for (int k = 0; k < 64; k++) a += q[k] * Wo3[k * 16 + t];
        int oi = r * 16 + t;
        if (oi < out_size) out[oi] = a;
    }
    if (r == 0 && t >= 16 && t < 19) {
        int oi = 1024 + (t - 16);
        if (oi < out_size) out[oi] = eta[t - 16];
    }
}

// ---------------- launch --------------------------------------------------------
extern "C" void kernel_launch(void* const* d_in, const int* in_sizes, int n_in,
                              void* d_out, int out_size) {
    const float* nf    = (const float*)d_in[0];
    const float* ea0   = (const float*)d_in[1];
    const float* ea1   = (const float*)d_in[2];
    const float* ea2   = (const float*)d_in[3];
    const float* temb  = (const float*)d_in[4];
    const float* etg   = (const float*)d_in[5];
    const float* eta   = (const float*)d_in[6];
    const float* W1    = (const float*)d_in[7];
    const float* as1   = (const float*)d_in[8];
    const float* ad1   = (const float*)d_in[9];
    const float* We1   = (const float*)d_in[10];
    const float* ae1   = (const float*)d_in[11];
    const float* b1    = (const float*)d_in[12];
    const float* W2    = (const float*)d_in[13];
    const float* as2   = (const float*)d_in[14];
    const float* ad2   = (const float*)d_in[15];
    const float* We2   = (const float*)d_in[16];
    const float* ae2   = (const float*)d_in[17];
    const float* b2    = (const float*)d_in[18];
    const float* pW    = (const float*)d_in[19];
    const float* pb    = (const float*)d_in[20];
    const float* Wo1   = (const float*)d_in[21];
    const float* bo1   = (const float*)d_in[22];
    const float* Wo2   = (const float*)d_in[23];
    const float* bo2   = (const float*)d_in[24];
    const float* Wo3   = (const float*)d_in[25];
    const float* bo3   = (const float*)d_in[26];
    const int* ntype   = (const int*)d_in[27];
    const int* ei0     = (const int*)d_in[28];
    const int* ei1     = (const int*)d_in[29];
    const int* ei2     = (const int*)d_in[30];
    const int* mask    = (const int*)d_in[31];
    float* out = (float*)d_out;

    k_zero_easum<<<1, 32>>>();
    { dim3 g(147, 3); k_easum<<<g, 256>>>(ea0, ea1, ea2); }
    k_setup<<<1, 256>>>(temb, etg, eta, W1, We1, ae1, We2, ae2);

    // CSR build, all 3 types batched
    k_zero_deg<<<586, 256>>>();
    { dim3 g(586, 3); k_deg<<<g, 1024>>>(ei0, ei1, ei2); }
    { dim3 g(NCHUNK, 3); k_partial<<<g, 512>>>(); }
    k_scanb<<<1, 32>>>();
    { dim3 g(NCHUNK, 3); k_scan2<<<g, 512>>>(); }
    { dim3 g(586, 3); k_fill<<<g, 1024>>>(ei0, ei1, ei2); }
    { dim3 g(2344, 3); k_edot<<<g, 256>>>(ea0, ea1, ea2); }

    // layer 1 (all types)
    { dim3 g(12500, 3); k_proj1<<<g, 128>>>(nf, ntype, W1, as1, ad1); }
    { dim3 g(6250, 3); k_gather<4, 1><<<g, 256>>>(b1); }
    // layer 2 (all types)
    { dim3 g(782, 3); gemm128<<<g, 256>>>(W2); }
    { dim3 g(6250, 3); k_s2<<<g, 256>>>(as2, ad2); }
    { dim3 g(6250, 3); k_gather<1, 2><<<g, 256>>>(b2); }
    k_combine<<<6250, 256>>>();

    k_scores<<<6242, 256>>>(pW, pb);
    k_stats<<<64, 256>>>(mask);
    k_pooled<<<391, 256>>>(mask);
    k_q1<<<64, 128>>>(Wo1, bo1);
    k_q2<<<64, 64>>>(Wo2, bo2);
    k_q3<<<64, 32>>>(Wo3, bo3, eta, out, out_size);
}

// round 5
// speedup vs baseline: 2.0721x; 1.2066x over previous
#include <cuda_runtime.h>
#include <math.h>
#include <stdint.h>

#define Nn 50000
#define Ee 600000
#define Rr 64
#define Vv 49936
#define HDim 128
#define NHEAD 4
#define EDim 8
#define NCHUNK 98
#define GB 6250    // gather blocks per type
#define EB 2344    // edot blocks per type
#define MB 391     // gemm blocks per type (ceil(50000/128))

// ---------------- scratch ----------------------------------------------------
__device__ float g_h[3][(size_t)Nn * HDim];
__device__ float g_x2[3][(size_t)Nn * HDim];
__device__ float g_acc[(size_t)Nn * HDim];
__device__ float g_ssrc[3][Nn * NHEAD];
__device__ float g_sdst[3][Nn * NHEAD];
__device__ float g_aloop[3][Nn * NHEAD];
__device__ float g_ssrc2[3][Nn];
__device__ float g_sdst2[3][Nn];
__device__ float g_aloop2[3][Nn];
__device__ int   g_deg[3][Nn];
__device__ int   g_cursor[3][Nn];
__device__ int   g_rowptr[3][Nn + 1];
__device__ int   g_bsum[3][NCHUNK];
__device__ int   g_csr_src[3][Ee];
__device__ int   g_csr_eid[3][Ee];
__device__ float g_edot1[3][(size_t)Ee * 4];
__device__ float g_edot2[3][Ee];
__device__ float g_scores[Vv];
__device__ float g_pmax[Rr], g_pden[Rr];
__device__ int   g_pcnt[Rr];
__device__ float g_pooled[Rr * HDim];
__device__ float g_q1[Rr * HDim];
__device__ float g_q2[Rr * 64];
__device__ float g_gate[3], g_wts[3];
__device__ float g_Wt[3][2][HDim];
__device__ float g_v1[3][NHEAD][EDim];
__device__ float g_v2[3][EDim];
__device__ float g_edl1[3][NHEAD];
__device__ float g_edl2[3];
__device__ float g_easum[3][EDim];
__device__ float g_was1[3][NHEAD][9];
__device__ float g_wad1[3][NHEAD][9];
__device__ float g_cA1[3][2][NHEAD];
__device__ float g_cD1[3][2][NHEAD];
__device__ float g_wa2[3][HDim];
__device__ float g_wd2[3][HDim];

__device__ __forceinline__ uint32_t f2tf32(float f) {
    uint32_t u; asm("cvt.rna.tf32.f32 %0, %1;" : "=r"(u) : "f"(f)); return u;
}

#define MMA_TF32(d, a, b) \
    asm volatile("mma.sync.aligned.m16n8k8.row.col.f32.tf32.tf32.f32 " \
        "{%0,%1,%2,%3}, {%4,%5,%6,%7}, {%8,%9}, {%0,%1,%2,%3};" \
        : "+f"(d[0]), "+f"(d[1]), "+f"(d[2]), "+f"(d[3]) \
        : "r"(a[0]), "r"(a[1]), "r"(a[2]), "r"(a[3]), "r"(b[0]), "r"(b[1]))

// ---------------- setup -------------------------------------------------------
__global__ void k_zero_easum() {
    int t = threadIdx.x;
    if (t < 24) ((float*)g_easum)[t] = 0.f;
}

__global__ void k_easum(const float* __restrict__ ea0, const float* __restrict__ ea1,
                        const float* __restrict__ ea2) {
    const float* ea = blockIdx.y == 0 ? ea0 : (blockIdx.y == 1 ? ea1 : ea2);
    __shared__ float s[EDim];
    if (threadIdx.x < EDim) s[threadIdx.x] = 0.f;
    __syncthreads();
    float loc[EDim];
#pragma unroll
    for (int k = 0; k < EDim; k++) loc[k] = 0.f;
    int base = blockIdx.x * 4096;
    int lim = base + 4096; if (lim > Ee) lim = Ee;
    for (int e = base + threadIdx.x; e < lim; e += 256) {
        const float4* p = (const float4*)(ea + (size_t)e * 8);
        float4 a = p[0], b = p[1];
        loc[0] += a.x; loc[1] += a.y; loc[2] += a.z; loc[3] += a.w;
        loc[4] += b.x; loc[5] += b.y; loc[6] += b.z; loc[7] += b.w;
    }
#pragma unroll
    for (int k = 0; k < EDim; k++) atomicAdd(&s[k], loc[k]);
    __syncthreads();
    if (threadIdx.x < EDim) atomicAdd(&g_easum[blockIdx.y][threadIdx.x], s[threadIdx.x]);
}

__global__ void k_setup(const float* __restrict__ temb, const float* __restrict__ etg,
                        const float* __restrict__ eta, const float* __restrict__ W1,
                        const float* __restrict__ We1, const float* __restrict__ ae1,
                        const float* __restrict__ We2, const float* __restrict__ ae2,
                        const float* __restrict__ as1, const float* __restrict__ ad1,
                        const float* __restrict__ W2, const float* __restrict__ as2,
                        const float* __restrict__ ad2) {
    int t = threadIdx.x;
    if (t < 3) g_gate[t] = 1.f / (1.f + __expf(-etg[t]));
    if (t == 0) {
        float m = fmaxf(eta[0], fmaxf(eta[1], eta[2]));
        float e0 = __expf(eta[0] - m), e1 = __expf(eta[1] - m), e2 = __expf(eta[2] - m);
        float s = e0 + e1 + e2;
        g_wts[0] = e0 / s; g_wts[1] = e1 / s; g_wts[2] = e2 / s;
    }
    __syncthreads();
    for (int idx = t; idx < 3 * 2 * HDim; idx += 256) {
        int i = idx / (2 * HDim); int r = idx % (2 * HDim);
        int ty = r / HDim; int j = r % HDim;
        float s = 0.f;
        for (int k = 0; k < 32; k++)
            s += temb[ty * 32 + k] * W1[i * 41 * HDim + (9 + k) * HDim + j];
        g_Wt[i][ty][j] = s;
    }
    for (int idx = t; idx < 3 * NHEAD * EDim; idx += 256) {
        int i = idx / 32; int h = (idx % 32) / 8; int k = idx % 8;
        float s = 0.f;
        for (int c = 0; c < 32; c++)
            s += We1[i * EDim * HDim + k * HDim + h * 32 + c] * ae1[i * NHEAD * 32 + h * 32 + c];
        g_v1[i][h][k] = g_gate[i] * s;
    }
    for (int idx = t; idx < 3 * EDim; idx += 256) {
        int i = idx / 8; int k = idx % 8;
        float s = 0.f;
        for (int c = 0; c < HDim; c++)
            s += We2[i * EDim * HDim + k * HDim + c] * ae2[i * HDim + c];
        g_v2[i][k] = g_gate[i] * s;
    }
    // was1/wad1: [3][4][9]
    for (int idx = t; idx < 108; idx += 256) {
        int i = idx / 36; int h = (idx % 36) / 9; int k = idx % 9;
        float sa = 0.f, sd = 0.f;
        for (int c = 0; c < 32; c++) {
            float w = W1[i * 41 * HDim + k * HDim + h * 32 + c];
            sa += w * as1[i * HDim + h * 32 + c];
            sd += w * ad1[i * HDim + h * 32 + c];
        }
        g_was1[i][h][k] = sa;
        g_wad1[i][h][k] = sd;
    }
    // wa2/wd2: [3][128]
    for (int idx = t; idx < 3 * HDim; idx += 256) {
        int i = idx / HDim; int k = idx % HDim;
        float sa = 0.f, sd = 0.f;
        for (int j = 0; j < HDim; j++) {
            float w = W2[(size_t)i * HDim * HDim + k * HDim + j];
            sa += w * as2[i * HDim + j];
            sd += w * ad2[i * HDim + j];
        }
        g_wa2[i][k] = sa;
        g_wd2[i][k] = sd;
    }
    __syncthreads();
    if (t < 12) {
        int i = t / 4, h = t % 4;
        float s = 0.f;
        for (int k = 0; k < EDim; k++) s += (g_easum[i][k] / (float)Ee) * g_v1[i][h][k];
        g_edl1[i][h] = s;
    }
    if (t >= 32 && t < 35) {
        int i = t - 32;
        float s = 0.f;
        for (int k = 0; k < EDim; k++) s += (g_easum[i][k] / (float)Ee) * g_v2[i][k];
        g_edl2[i] = s;
    }
    // cA1/cD1: [3][2][4]
    if (t >= 64 && t < 88) {
        int r = t - 64;
        int i = r / 8; int ty = (r % 8) / 4; int h = r % 4;
        float sa = 0.f, sd = 0.f;
        for (int c = 0; c < 32; c++) {
            float w = g_Wt[i][ty][h * 32 + c];
            sa += w * as1[i * HDim + h * 32 + c];
            sd += w * ad1[i * HDim + h * 32 + c];
        }
        g_cA1[i][ty][h] = sa;
        g_cD1[i][ty][h] = sd;
    }
}

// ---------------- CSR build ----------------------------------------------------
__global__ void k_zero_deg() {
    int i = blockIdx.x * 256 + threadIdx.x;
    if (i < 3 * Nn) ((int*)g_deg)[i] = 0;
}

__global__ void k_deg(const int* __restrict__ ei0, const int* __restrict__ ei1,
                      const int* __restrict__ ei2) {
    const int* ei = blockIdx.y == 0 ? ei0 : (blockIdx.y == 1 ? ei1 : ei2);
    int e = blockIdx.x * 1024 + threadIdx.x;
    if (e < Ee) atomicAdd(&g_deg[blockIdx.y][ei[Ee + e]], 1);
}

__global__ void k_partial() {
    __shared__ int s[512];
    int ty = blockIdx.y;
    int t = threadIdx.x;
    int i = blockIdx.x * 512 + t;
    s[t] = (i < Nn) ? g_deg[ty][i] : 0;
    __syncthreads();
    for (int off = 256; off > 0; off >>= 1) {
        if (t < off) s[t] += s[t + off];
        __syncthreads();
    }
    if (t == 0) g_bsum[ty][blockIdx.x] = s[0];
}

__global__ void k_scanb() {
    int t = threadIdx.x;
    if (t < 3) {
        int s = 0;
        for (int b = 0; b < NCHUNK; b++) { int v = g_bsum[t][b]; g_bsum[t][b] = s; s += v; }
    }
}

__global__ void k_scan2() {
    __shared__ int s[512];
    int ty = blockIdx.y;
    int t = threadIdx.x;
    int i = blockIdx.x * 512 + t;
    int v = (i < Nn) ? g_deg[ty][i] : 0;
    s[t] = v;
    __syncthreads();
    for (int off = 1; off < 512; off <<= 1) {
        int x = 0;
        if (t >= off) x = s[t - off];
        __syncthreads();
        s[t] += x;
        __syncthreads();
    }
    int excl = s[t] - v + g_bsum[ty][blockIdx.x];
    if (i < Nn) {
        g_rowptr[ty][i] = excl;
        g_cursor[ty][i] = excl;
        if (i == Nn - 1) g_rowptr[ty][Nn] = excl + v;
    }
}

__global__ void k_fill(const int* __restrict__ ei0, const int* __restrict__ ei1,
                       const int* __restrict__ ei2) {
    int ty = blockIdx.y;
    const int* ei = ty == 0 ? ei0 : (ty == 1 ? ei1 : ei2);
    int e = blockIdx.x * 1024 + threadIdx.x;
    if (e >= Ee) return;
    int src = ei[e], dst = ei[Ee + e];
    int pos = atomicAdd(&g_cursor[ty][dst], 1);
    g_csr_src[ty][pos] = src;
    g_csr_eid[ty][pos] = e;
}

// per-edge attention edge-term dots (type-sequential 1D grid)
__global__ void k_edot(const float* __restrict__ ea0, const float* __restrict__ ea1,
                       const float* __restrict__ ea2) {
    int i = blockIdx.x / EB;
    int bx = blockIdx.x % EB;
    const float* ea = i == 0 ? ea0 : (i == 1 ? ea1 : ea2);
    int e = bx * 256 + threadIdx.x;
    if (e >= Ee) return;
    const float4* p = (const float4*)(ea + (size_t)e * 8);
    float4 a0 = p[0], a1 = p[1];
    float4 d1;
    {
        const float* v = g_v1[i][0];
        d1.x = a0.x*v[0]+a0.y*v[1]+a0.z*v[2]+a0.w*v[3]+a1.x*v[4]+a1.y*v[5]+a1.z*v[6]+a1.w*v[7];
    }
    {
        const float* v = g_v1[i][1];
        d1.y = a0.x*v[0]+a0.y*v[1]+a0.z*v[2]+a0.w*v[3]+a1.x*v[4]+a1.y*v[5]+a1.z*v[6]+a1.w*v[7];
    }
    {
        const float* v = g_v1[i][2];
        d1.z = a0.x*v[0]+a0.y*v[1]+a0.z*v[2]+a0.w*v[3]+a1.x*v[4]+a1.y*v[5]+a1.z*v[6]+a1.w*v[7];
    }
    {
        const float* v = g_v1[i][3];
        d1.w = a0.x*v[0]+a0.y*v[1]+a0.z*v[2]+a0.w*v[3]+a1.x*v[4]+a1.y*v[5]+a1.z*v[6]+a1.w*v[7];
    }
    ((float4*)g_edot1[i])[e] = d1;
    const float* v = g_v2[i];
    g_edot2[i][e] = a0.x*v[0]+a0.y*v[1]+a0.z*v[2]+a0.w*v[3]+a1.x*v[4]+a1.y*v[5]+a1.z*v[6]+a1.w*v[7];
}

// ---------------- layer 1: h projection only (no shuffles) ---------------------
__global__ void k_projA(const float* __restrict__ nf, const int* __restrict__ ntype,
                        const float* __restrict__ W1) {
    int i = blockIdx.y;
    const float* W1i = W1 + (size_t)i * 41 * HDim;
    int j = threadIdx.x;
    float w[9];
#pragma unroll
    for (int k = 0; k < 9; k++) w[k] = W1i[k * HDim + j];
    float wt0 = g_Wt[i][0][j], wt1 = g_Wt[i][1][j];
    float* hout = g_h[i];
    int nb = blockIdx.x * 4;
#pragma unroll
    for (int nn = 0; nn < 4; nn++) {
        int n = nb + nn;
        const float* row = nf + (size_t)n * 9;
        float acc = ntype[n] ? wt1 : wt0;
#pragma unroll
        for (int k = 0; k < 9; k++) acc += row[k] * w[k];
        hout[(size_t)n * HDim + j] = acc;
    }
}

// per-node layer-1 attn logits via precomputed 9-dim dots
__global__ void k_sattn1(const float* __restrict__ nf, const int* __restrict__ ntype) {
    int n = blockIdx.x * 256 + threadIdx.x;
    if (n >= Nn) return;
    float f[9];
#pragma unroll
    for (int k = 0; k < 9; k++) f[k] = nf[(size_t)n * 9 + k];
    int ty = ntype[n];
#pragma unroll
    for (int i = 0; i < 3; i++) {
#pragma unroll
        for (int h = 0; h < 4; h++) {
            float ss = g_cA1[i][ty][h];
            float sd = g_cD1[i][ty][h];
#pragma unroll
            for (int k = 0; k < 9; k++) {
                ss += f[k] * g_was1[i][h][k];
                sd += f[k] * g_wad1[i][h][k];
            }
            g_ssrc[i][n * 4 + h] = ss;
            g_sdst[i][n * 4 + h] = sd;
            float a = ss + sd + g_edl1[i][h];
            a = a > 0.f ? a : 0.2f * a;
            g_aloop[i][n * 4 + h] = a;
        }
    }
}

// ---------------- gather layer 1 (+ fused layer-2 logits epilogue) -------------
__global__ void k_gather1(const float* __restrict__ b1) {
    int i = blockIdx.x / GB;
    int bx = blockIdx.x % GB;
    int warp = threadIdx.x >> 5;
    int n = bx * 8 + warp;
    if (n >= Nn) return;
    int lane = threadIdx.x & 31;
    int hh = lane >> 3;

    const float* hbase = g_h[i];
    const float* ssrc = g_ssrc[i];
    const int* csrs = g_csr_src[i];
    const int* csre = g_csr_eid[i];
    const float* ed1 = g_edot1[i];

    float sdv = g_sdst[i][n * 4 + hh];
    float alv = g_aloop[i][n * 4 + hh];

    float4 acc = ((const float4*)(hbase + (size_t)n * HDim))[lane];
    float den = 1.f;

    int k = g_rowptr[i][n];
    int end = g_rowptr[i][n + 1];
#pragma unroll 1
    for (; k + 1 < end; k += 2) {
        int s0 = csrs[k],     e0 = csre[k];
        int s1 = csrs[k + 1], e1 = csre[k + 1];
        float4 h0 = ((const float4*)(hbase + (size_t)s0 * HDim))[lane];
        float4 h1 = ((const float4*)(hbase + (size_t)s1 * HDim))[lane];
        float a0 = ssrc[s0 * 4 + hh] + sdv + ed1[(size_t)e0 * 4 + hh];
        float a1 = ssrc[s1 * 4 + hh] + sdv + ed1[(size_t)e1 * 4 + hh];
        a0 = a0 > 0.f ? a0 : 0.2f * a0;
        a1 = a1 > 0.f ? a1 : 0.2f * a1;
        float x0 = __expf(a0 - alv);
        float x1 = __expf(a1 - alv);
        den += x0 + x1;
        acc.x += x0 * h0.x + x1 * h1.x;
        acc.y += x0 * h0.y + x1 * h1.y;
        acc.z += x0 * h0.z + x1 * h1.z;
        acc.w += x0 * h0.w + x1 * h1.w;
    }
    if (k < end) {
        int s0 = csrs[k], e0 = csre[k];
        float4 h0 = ((const float4*)(hbase + (size_t)s0 * HDim))[lane];
        float a0 = ssrc[s0 * 4 + hh] + sdv + ed1[(size_t)e0 * 4 + hh];
        a0 = a0 > 0.f ? a0 : 0.2f * a0;
        float x0 = __expf(a0 - alv);
        den += x0;
        acc.x += x0 * h0.x; acc.y += x0 * h0.y; acc.z += x0 * h0.z; acc.w += x0 * h0.w;
    }

    float inv = 1.f / (den + 1e-16f);
    float4 bv = ((const float4*)(b1 + i * HDim))[lane];
    float4 v;
    v.x = acc.x * inv + bv.x;  v.x = v.x > 0.f ? v.x : (expf(v.x) - 1.f);
    v.y = acc.y * inv + bv.y;  v.y = v.y > 0.f ? v.y : (expf(v.y) - 1.f);
    v.z = acc.z * inv + bv.z;  v.z = v.z > 0.f ? v.z : (expf(v.z) - 1.f);
    v.w = acc.w * inv + bv.w;  v.w = v.w > 0.f ? v.w : (expf(v.w) - 1.f);
    ((float4*)(g_x2[i] + (size_t)n * HDim))[lane] = v;

    // fused layer-2 logits: ss2 = x2 . wa2, sd2 = x2 . wd2
    float4 wa = ((const float4*)g_wa2[i])[lane];
    float4 wd = ((const float4*)g_wd2[i])[lane];
    float ss = v.x * wa.x + v.y * wa.y + v.z * wa.z + v.w * wa.w;
    float sd = v.x * wd.x + v.y * wd.y + v.z * wd.z + v.w * wd.w;
#pragma unroll
    for (int o = 16; o > 0; o >>= 1) {
        ss += __shfl_xor_sync(0xffffffffu, ss, o);
        sd += __shfl_xor_sync(0xffffffffu, sd, o);
    }
    if (lane == 0) {
        g_ssrc2[i][n] = ss;
        g_sdst2[i][n] = sd;
        float a = ss + sd + g_edl2[i];
        a = a > 0.f ? a : 0.2f * a;
        g_aloop2[i][n] = a;
    }
}

// ---------------- tf32 tensor-core GEMM: g_h[i] = g_x2[i] @ W2[i] ---------------
__global__ void gemm_tf32(const float* __restrict__ W2) {
    int ty = blockIdx.x / MB;
    int bx = blockIdx.x % MB;
    const float* X = g_x2[ty];
    float* Y = g_h[ty];
    const float* W = W2 + (size_t)ty * HDim * HDim;
    __shared__ uint32_t Xs[128][36];
    __shared__ uint32_t Ws[32][136];
    int tid = threadIdx.x;
    int wid = tid >> 5, lane = tid & 31;
    int wm = wid & 3, wn = wid >> 2;
    int g = lane >> 2, c = lane & 3;
    int m0 = bx * 128;

    float acc[2][8][4];
#pragma unroll
    for (int mf = 0; mf < 2; mf++)
#pragma unroll
        for (int nf = 0; nf < 8; nf++)
#pragma unroll
            for (int q = 0; q < 4; q++) acc[mf][nf][q] = 0.f;

    for (int kt = 0; kt < 4; kt++) {
#pragma unroll
        for (int it = 0; it < 4; it++) {
            int idx = tid + it * 256;       // 0..1023
            int row = idx >> 3;
            int q4 = idx & 7;
            int n = m0 + row;
            float4 xv = (n < Nn) ? ((const float4*)(X + (size_t)n * 128 + kt * 32))[q4]
                                 : make_float4(0.f, 0.f, 0.f, 0.f);
            Xs[row][q4 * 4 + 0] = f2tf32(xv.x);
            Xs[row][q4 * 4 + 1] = f2tf32(xv.y);
            Xs[row][q4 * 4 + 2] = f2tf32(xv.z);
            Xs[row][q4 * 4 + 3] = f2tf32(xv.w);
        }
#pragma unroll
        for (int it = 0; it < 4; it++) {
            int idx = tid + it * 256;
            int kk = idx >> 5;
            int q4 = idx & 31;
            float4 wv = ((const float4*)(W + (size_t)(kt * 32 + kk) * 128))[q4];
            Ws[kk][q4 * 4 + 0] = f2tf32(wv.x);
            Ws[kk][q4 * 4 + 1] = f2tf32(wv.y);
            Ws[kk][q4 * 4 + 2] = f2tf32(wv.z);
            Ws[kk][q4 * 4 + 3] = f2tf32(wv.w);
        }
        __syncthreads();
#pragma unroll
        for (int ks = 0; ks < 4; ks++) {
            int k0 = ks * 8;
            uint32_t a[2][4], b[8][2];
#pragma unroll
            for (int mf = 0; mf < 2; mf++) {
                int row = wm * 32 + mf * 16;
                a[mf][0] = Xs[row + g][k0 + c];
                a[mf][1] = Xs[row + g + 8][k0 + c];
                a[mf][2] = Xs[row + g][k0 + c + 4];
                a[mf][3] = Xs[row + g + 8][k0 + c + 4];
            }
#pragma unroll
            for (int nf = 0; nf < 8; nf++) {
                int col = wn * 64 + nf * 8 + g;
                b[nf][0] = Ws[k0 + c][col];
                b[nf][1] = Ws[k0 + c + 4][col];
            }
#pragma unroll
            for (int mf = 0; mf < 2; mf++)
#pragma unroll
                for (int nf = 0; nf < 8; nf++)
                    MMA_TF32(acc[mf][nf], a[mf], b[nf]);
        }
        __syncthreads();
    }
#pragma unroll
    for (int mf = 0; mf < 2; mf++) {
#pragma unroll
        for (int nf = 0; nf < 8; nf++) {
            int row0 = m0 + wm * 32 + mf * 16 + g;
            int col = wn * 64 + nf * 8 + c * 2;
            if (row0 < Nn)
                *(float2*)(Y + (size_t)row0 * 128 + col) = make_float2(acc[mf][nf][0], acc[mf][nf][1]);
            int row1 = row0 + 8;
            if (row1 < Nn)
                *(float2*)(Y + (size_t)row1 * 128 + col) = make_float2(acc[mf][nf][2], acc[mf][nf][3]);
        }
    }
}

// ---------------- gather layer 2 -------------------------------------------------
__global__ void k_gather2(const float* __restrict__ b2) {
    int i = blockIdx.x / GB;
    int bx = blockIdx.x % GB;
    int warp = threadIdx.x >> 5;
    int n = bx * 8 + warp;
    if (n >= Nn) return;
    int lane = threadIdx.x & 31;

    const float* hbase = g_h[i];
    const float* ssrc = g_ssrc2[i];
    const int* csrs = g_csr_src[i];
    const int* csre = g_csr_eid[i];
    const float* ed2 = g_edot2[i];

    float sdv = g_sdst2[i][n];
    float alv = g_aloop2[i][n];

    float4 acc = ((const float4*)(hbase + (size_t)n * HDim))[lane];
    float den = 1.f;

    int k = g_rowptr[i][n];
    int end = g_rowptr[i][n + 1];
#pragma unroll 1
    for (; k + 1 < end; k += 2) {
        int s0 = csrs[k],     e0 = csre[k];
        int s1 = csrs[k + 1], e1 = csre[k + 1];
        float4 h0 = ((const float4*)(hbase + (size_t)s0 * HDim))[lane];
        float4 h1 = ((const float4*)(hbase + (size_t)s1 * HDim))[lane];
        float a0 = ssrc[s0] + sdv + ed2[e0];
        float a1 = ssrc[s1] + sdv + ed2[e1];
        a0 = a0 > 0.f ? a0 : 0.2f * a0;
        a1 = a1 > 0.f ? a1 : 0.2f * a1;
        float x0 = __expf(a0 - alv);
        float x1 = __expf(a1 - alv);
        den += x0 + x1;
        acc.x += x0 * h0.x + x1 * h1.x;
        acc.y += x0 * h0.y + x1 * h1.y;
        acc.z += x0 * h0.z + x1 * h1.z;
        acc.w += x0 * h0.w + x1 * h1.w;
    }
    if (k < end) {
        int s0 = csrs[k], e0 = csre[k];
        float4 h0 = ((const float4*)(hbase + (size_t)s0 * HDim))[lane];
        float a0 = ssrc[s0] + sdv + ed2[e0];
        a0 = a0 > 0.f ? a0 : 0.2f * a0;
        float x0 = __expf(a0 - alv);
        den += x0;
        acc.x += x0 * h0.x; acc.y += x0 * h0.y; acc.z += x0 * h0.z; acc.w += x0 * h0.w;
    }

    float inv = 1.f / (den + 1e-16f);
    float w = g_wts[i];
    float4 bv = ((const float4*)(b2 + i * HDim))[lane];
    float4 v;
    v.x = (acc.x * inv + bv.x) * w;
    v.y = (acc.y * inv + bv.y) * w;
    v.z = (acc.z * inv + bv.z) * w;
    v.w = (acc.w * inv + bv.w) * w;
    ((float4*)(g_x2[i] + (size_t)n * HDim))[lane] = v;
}

__global__ void k_combine() {
    int idx = blockIdx.x * 256 + threadIdx.x;
    if (idx >= Nn * HDim / 4) return;
    float4 a = ((const float4*)g_x2[0])[idx];
    float4 b = ((const float4*)g_x2[1])[idx];
    float4 c = ((const float4*)g_x2[2])[idx];
    float4 v;
    v.x = a.x + b.x + c.x;
    v.y = a.y + b.y + c.y;
    v.z = a.z + b.z + c.z;
    v.w = a.w + b.w + c.w;
    ((float4*)g_acc)[idx] = v;
}

// ---------------- pooling / readout ----------------------------------------------
__global__ void k_scores(const float* __restrict__ pW, const float* __restrict__ pb) {
    int v = blockIdx.x * 8 + (threadIdx.x >> 5);
    if (v >= Vv) return;
    int lane = threadIdx.x & 31;
    float s = 0.f;
#pragma unroll
    for (int k = 0; k < 4; k++) {
        int j = lane + k * 32;
        s += g_acc[(size_t)(Rr + v) * HDim + j] * pW[j];
    }
#pragma unroll
    for (int o = 16; o > 0; o >>= 1) s += __shfl_xor_sync(0xffffffffu, s, o);
    if (lane == 0) g_scores[v] = s + pb[0];
}

__global__ void k_stats(const int* __restrict__ mask) {
    int r = blockIdx.x; int t = threadIdx.x;
    __shared__ float red[256];
    __shared__ int redi[256];
    const int* mrow = mask + (size_t)r * Vv;
    float mx = -3.0e38f;
    for (int v = t; v < Vv; v += 256) if (mrow[v]) mx = fmaxf(mx, g_scores[v]);
    red[t] = mx; __syncthreads();
    for (int s = 128; s > 0; s >>= 1) { if (t < s) red[t] = fmaxf(red[t], red[t + s]); __syncthreads(); }
    float m = red[0]; __syncthreads();
    float sm = 0.f; int c = 0;
    for (int v = t; v < Vv; v += 256)
        if (mrow[v]) { sm += __expf(g_scores[v] - m); c++; }
    red[t] = sm; redi[t] = c; __syncthreads();
    for (int s = 128; s > 0; s >>= 1) {
        if (t < s) { red[t] += red[t + s]; redi[t] += redi[t + s]; }
        __syncthreads();
    }
    if (t == 0) { g_pmax[r] = m; g_pden[r] = red[0]; g_pcnt[r] = redi[0]; }
    if (t < HDim) g_pooled[r * HDim + t] = 0.f;
}

__global__ void k_pooled(const int* __restrict__ mask) {
    __shared__ float aws[64 * 128];
    int t = threadIdx.x;
    int vb = blockIdx.x * 128;
    int nv = Vv - vb; if (nv > 128) nv = 128;
    for (int idx = t; idx < 64 * 128; idx += 256) {
        int r = idx >> 7, v = idx & 127;
        float aw = 0.f;
        if (v < nv) {
            int mv = mask[(size_t)r * Vv + vb + v];
            if (mv && g_pcnt[r] > 0)
                aw = __expf(g_scores[vb + v] - g_pmax[r]) / g_pden[r];
        }
        aws[idx] = aw;
    }
    __syncthreads();
    int rg = t >> 7, c = t & 127;
    float acc[32];
#pragma unroll
    for (int rr = 0; rr < 32; rr++) acc[rr] = 0.f;
    for (int v = 0; v < nv; v++) {
        float vx = g_acc[(size_t)(Rr + vb + v) * HDim + c];
#pragma unroll
        for (int rr = 0; rr < 32; rr++) acc[rr] += aws[(rg * 32 + rr) * 128 + v] * vx;
    }
    for (int rr = 0; rr < 32; rr++)
        atomicAdd(&g_pooled[(rg * 32 + rr) * 128 + c], acc[rr]);
}

__global__ void k_q1(const float* __restrict__ Wo1, const float* __restrict__ bo1) {
    __shared__ float comb[256];
    int r = blockIdx.x, t = threadIdx.x;
    comb[t] = g_acc[r * HDim + t];
    comb[128 + t] = g_pooled[r * HDim + t];
    __syncthreads();
    float a = bo1[t];
    for (int k = 0; k < 256; k++) a += comb[k] * Wo1[k * 128 + t];
    g_q1[r * 128 + t] = fmaxf(a, 0.f);
}

__global__ void k_q2(const float* __restrict__ Wo2, const float* __restrict__ bo2) {
    __shared__ float q[128];
    int r = blockIdx.x, t = threadIdx.x;
    q[t] = g_q1[r * 128 + t]; q[64 + t] = g_q1[r * 128 + 64 + t];
    __syncthreads();
    float a = bo2[t];
    for (int k = 0; k < 128; k++) a += q[k] * Wo2[k * 64 + t];
    g_q2[r * 64 + t] = fmaxf(a, 0.f);
}

__global__ void k_q3(const float* __restrict__ Wo3, const float* __restrict__ bo3,
                     const float* __restrict__ eta, float* __restrict__ out, int out_size) {
    __shared__ float q[64];
    int r = blockIdx.x, t = threadIdx.x;
    q[t] = g_q2[r * 64 + t]; q[32 + t] = g_q2[r * 64 + 32 + t];
    __syncthreads();
    if (t < 16) {
        float a = bo3[t];
        for (int k = 0; k < 64; k++) a += q[k] * Wo3[k * 16 + t];
        int oi = r * 16 + t;
        if (oi < out_size) out[oi] = a;
    }
    if (r == 0 && t >= 16 && t < 19) {
        int oi = 1024 + (t - 16);
        if (oi < out_size) out[oi] = eta[t - 16];
    }
}

// ---------------- launch ----------------------------------------------------------
extern "C" void kernel_launch(void* const* d_in, const int* in_sizes, int n_in,
                              void* d_out, int out_size) {
    const float* nf    = (const float*)d_in[0];
    const float* ea0   = (const float*)d_in[1];
    const float* ea1   = (const float*)d_in[2];
    const float* ea2   = (const float*)d_in[3];
    const float* temb  = (const float*)d_in[4];
    const float* etg   = (const float*)d_in[5];
    const float* eta   = (const float*)d_in[6];
    const float* W1    = (const float*)d_in[7];
    const float* as1   = (const float*)d_in[8];
    const float* ad1   = (const float*)d_in[9];
    const float* We1   = (const float*)d_in[10];
    const float* ae1   = (const float*)d_in[11];
    const float* b1    = (const float*)d_in[12];
    const float* W2    = (const float*)d_in[13];
    const float* as2   = (const float*)d_in[14];
    const float* ad2   = (const float*)d_in[15];
    const float* We2   = (const float*)d_in[16];
    const float* ae2   = (const float*)d_in[17];
    const float* b2    = (const float*)d_in[18];
    const float* pW    = (const float*)d_in[19];
    const float* pb    = (const float*)d_in[20];
    const float* Wo1   = (const float*)d_in[21];
    const float* bo1   = (const float*)d_in[22];
    const float* Wo2   = (const float*)d_in[23];
    const float* bo2   = (const float*)d_in[24];
    const float* Wo3   = (const float*)d_in[25];
    const float* bo3   = (const float*)d_in[26];
    const int* ntype   = (const int*)d_in[27];
    const int* ei0     = (const int*)d_in[28];
    const int* ei1     = (const int*)d_in[29];
    const int* ei2     = (const int*)d_in[30];
    const int* mask    = (const int*)d_in[31];
    float* out = (float*)d_out;

    k_zero_easum<<<1, 32>>>();
    { dim3 g(147, 3); k_easum<<<g, 256>>>(ea0, ea1, ea2); }
    k_setup<<<1, 256>>>(temb, etg, eta, W1, We1, ae1, We2, ae2,
                        as1, ad1, W2, as2, ad2);

    // CSR build
    k_zero_deg<<<586, 256>>>();
    { dim3 g(586, 3); k_deg<<<g, 1024>>>(ei0, ei1, ei2); }
    { dim3 g(NCHUNK, 3); k_partial<<<g, 512>>>(); }
    k_scanb<<<1, 32>>>();
    { dim3 g(NCHUNK, 3); k_scan2<<<g, 512>>>(); }
    { dim3 g(586, 3); k_fill<<<g, 1024>>>(ei0, ei1, ei2); }
    k_edot<<<3 * EB, 256>>>(ea0, ea1, ea2);

    // layer 1
    { dim3 g(12500, 3); k_projA<<<g, 128>>>(nf, ntype, W1); }
    k_sattn1<<<196, 256>>>(nf, ntype);
    k_gather1<<<3 * GB, 256>>>(b1);
    // layer 2
    gemm_tf32<<<3 * MB, 256>>>(W2);
    k_gather2<<<3 * GB, 256>>>(b2);
    k_combine<<<6250, 256>>>();

    k_scores<<<6242, 256>>>(pW, pb);
    k_stats<<<64, 256>>>(mask);
    k_pooled<<<391, 256>>>(mask);
    k_q1<<<64, 128>>>(Wo1, bo1);
    k_q2<<<64, 64>>>(Wo2, bo2);
    k_q3<<<64, 32>>>(Wo3, bo3, eta, out, out_size);
}